// round 4
// baseline (speedup 1.0000x reference)
#include <cuda_runtime.h>
#include <cuda_fp16.h>
#include <cstdint>
#include <math.h>

// ============================================================================
// ReasonNet via ldmatrix + mma.sync (HMMA), fp16 2-term split => fp32 accuracy.
// Round 4: BK=64 (half the barriers), 3-stage cp.async, fused QKV GEMM.
// B=16, T=1024, C=1024, K=8, H=1536.  M = B*T = 16384.
// ============================================================================

#define MDIM 16384
#define CDIM 1024
#define HDIM 1536
#define KNEI 8
#define TSEQ 1024
#define QKVLD 3072

#define BK 64
#define KSTRIDE 72                  // halfs per smem row (144B; LDSM conflict-free)
#define ROWB 144
#define STG_A_H 0
#define STG_A_L 18432               // 128*144
#define STG_B_H 36864
#define STG_B_L 55296
#define STG_BYTES 73728
#define MM_SMEM (3 * STG_BYTES)     // 221184 bytes

// ---------------------------------------------------------------------------
// Scratch (static device globals; runtime allocation forbidden).
// ---------------------------------------------------------------------------
__device__ float  g_qkv [(size_t)MDIM * QKVLD];   // fused q|k|v per hop
__device__ __half g_ctxh[(size_t)MDIM * CDIM];
__device__ __half g_ctxl[(size_t)MDIM * CDIM];
__device__ __half g_hh  [(size_t)MDIM * CDIM];
__device__ __half g_hl  [(size_t)MDIM * CDIM];
__device__ float  g_h32 [(size_t)MDIM * CDIM];
__device__ float  g_y   [(size_t)MDIM * CDIM];
__device__ __half g_yh  [(size_t)MDIM * CDIM];
__device__ __half g_yl  [(size_t)MDIM * CDIM];
__device__ float  g_f   [(size_t)MDIM * CDIM];
__device__ __half g_xh  [(size_t)MDIM * CDIM];
__device__ __half g_xl  [(size_t)MDIM * CDIM];
__device__ __half g_hidh[(size_t)MDIM * HDIM];
__device__ __half g_hidl[(size_t)MDIM * HDIM];
// Transposed + split weights: Wt[N][K] fp16 hi/lo.  QKV stacked (3072 rows).
__device__ __half g_wqkvh[(size_t)QKVLD * CDIM], g_wqkvl[(size_t)QKVLD * CDIM];
__device__ __half g_woh[(size_t)CDIM * CDIM], g_wol[(size_t)CDIM * CDIM];
__device__ __half g_w1h[(size_t)HDIM * CDIM], g_w1l[(size_t)HDIM * CDIM];
__device__ __half g_w2h[(size_t)CDIM * HDIM], g_w2l[(size_t)CDIM * HDIM];

// ---------------------------------------------------------------------------
// PTX helpers (sm_80-portable only)
// ---------------------------------------------------------------------------
__device__ __forceinline__ uint32_t smem_u32(const void* p) {
    uint32_t a;
    asm("{ .reg .u64 t; cvta.to.shared.u64 t, %1; cvt.u32.u64 %0, t; }"
        : "=r"(a) : "l"(p));
    return a;
}
__device__ __forceinline__ void cp16(uint32_t s, const void* g) {
    asm volatile("cp.async.cg.shared.global [%0], [%1], 16;" :: "r"(s), "l"(g) : "memory");
}
__device__ __forceinline__ void ldsm4(uint32_t* r, uint32_t addr) {
    asm volatile("ldmatrix.sync.aligned.m8n8.x4.shared.b16 {%0,%1,%2,%3}, [%4];"
                 : "=r"(r[0]), "=r"(r[1]), "=r"(r[2]), "=r"(r[3]) : "r"(addr));
}
__device__ __forceinline__ void mma16816(float* c, const uint32_t* a, const uint32_t* b) {
    asm volatile(
        "mma.sync.aligned.m16n8k16.row.col.f32.f16.f16.f32 "
        "{%0,%1,%2,%3}, {%4,%5,%6,%7}, {%8,%9}, {%0,%1,%2,%3};"
        : "+f"(c[0]), "+f"(c[1]), "+f"(c[2]), "+f"(c[3])
        : "r"(a[0]), "r"(a[1]), "r"(a[2]), "r"(a[3]), "r"(b[0]), "r"(b[1]));
}

// ---------------------------------------------------------------------------
// fp16-split GEMM: C[M,N] = (Ah+Al)[M,K] @ (Bh+Bl)[N,K]^T   (fp32 accuracy)
// flags: bit0 relu, bit1 write fp16 split (Chh/Chl), bit2 write fp32 (Cf).
// 256 threads, 128x128 tile, BK=64, 3-stage cp.async pipeline.
// ---------------------------------------------------------------------------
__global__ __launch_bounds__(256, 1)
void mm_fp16x2_kernel(const __half* __restrict__ Ah, const __half* __restrict__ Al,
                      const __half* __restrict__ Bh, const __half* __restrict__ Bl,
                      float* __restrict__ Cf, __half* __restrict__ Chh,
                      __half* __restrict__ Chl, const float* __restrict__ bias,
                      int N, int K, int flags)
{
    extern __shared__ char smem[];
    const uint32_t sb = smem_u32(smem);
    const int tid  = threadIdx.x;
    const int wid  = tid >> 5;
    const int lane = tid & 31;
    const int bm   = blockIdx.y * 128;
    const int bn   = blockIdx.x * 128;
    const int wmB  = (wid >> 2) * 64;
    const int wn   = (wid & 3) * 32;
    const int ntiles = K / BK;

    // -------- producer addressing --------
    const int row = tid & 127;
    const int sg0 = tid >> 7;           // 0/1; this thread covers segs sg0+2q, q=0..3
    const __half* gAh = Ah + (size_t)(bm + row) * K;
    const __half* gAl = Al + (size_t)(bm + row) * K;
    const __half* gBh = Bh + (size_t)(bn + row) * K;
    const __half* gBl = Bl + (size_t)(bn + row) * K;
    const uint32_t doff = (uint32_t)row * ROWB;

    auto issue = [&](int kt, int s) {
        const uint32_t st = sb + (uint32_t)s * STG_BYTES;
        const size_t kof = (size_t)kt * BK;
#pragma unroll
        for (int qq = 0; qq < 4; qq++) {
            const int seg = sg0 + qq * 2;
            const uint32_t d = doff + seg * 16;
            const size_t g = kof + seg * 8;
            cp16(st + STG_A_H + d, gAh + g);
            cp16(st + STG_A_L + d, gAl + g);
            cp16(st + STG_B_H + d, gBh + g);
            cp16(st + STG_B_L + d, gBl + g);
        }
        asm volatile("cp.async.commit_group;" ::: "memory");
    };

    float acc[4][4][4];
#pragma unroll
    for (int i = 0; i < 4; i++)
#pragma unroll
        for (int j = 0; j < 4; j++)
#pragma unroll
            for (int l = 0; l < 4; l++) acc[i][j][l] = 0.f;

    issue(0, 0);
    issue(1, 1);

    // ldmatrix lane addressing
    const int arow  = lane & 15;
    const int acol8 = (lane >> 4) * 8;
    const int brow  = (lane & 7) + ((lane >> 4) << 3);
    const int bcol8 = ((lane >> 3) & 1) * 8;

    for (int kt = 0; kt < ntiles; kt++) {
        asm volatile("cp.async.wait_group 1;" ::: "memory");
        __syncthreads();
        if (kt + 2 < ntiles) issue(kt + 2, (kt + 2) % 3);   // overwrites stage kt-1: safe

        const uint32_t stg = sb + (uint32_t)(kt % 3) * STG_BYTES;
#pragma unroll
        for (int ks = 0; ks < 4; ks++) {
            const int kb = ks * 16;
            uint32_t ahf[4][4], alf[4][4], bhf[2][4], blf[2][4];
#pragma unroll
            for (int mt = 0; mt < 4; mt++) {
                const uint32_t off =
                    (uint32_t)((wmB + mt * 16 + arow) * KSTRIDE + kb + acol8) * 2;
                ldsm4(ahf[mt], stg + STG_A_H + off);
                ldsm4(alf[mt], stg + STG_A_L + off);
            }
#pragma unroll
            for (int nt2 = 0; nt2 < 2; nt2++) {
                const uint32_t off =
                    (uint32_t)((wn + nt2 * 16 + brow) * KSTRIDE + kb + bcol8) * 2;
                ldsm4(bhf[nt2], stg + STG_B_H + off);
                ldsm4(blf[nt2], stg + STG_B_L + off);
            }
#pragma unroll
            for (int mt = 0; mt < 4; mt++)
#pragma unroll
                for (int nt = 0; nt < 4; nt++) {
                    const uint32_t* bh = &bhf[nt >> 1][(nt & 1) * 2];
                    const uint32_t* bl = &blf[nt >> 1][(nt & 1) * 2];
                    mma16816(acc[mt][nt], ahf[mt], bh);   // hi*hi
                    mma16816(acc[mt][nt], ahf[mt], bl);   // hi*lo
                    mma16816(acc[mt][nt], alf[mt], bh);   // lo*hi
                }
        }
    }

    // -------- epilogue --------
    const int g = lane >> 2;
    const int t = lane & 3;
#pragma unroll
    for (int mt = 0; mt < 4; mt++)
#pragma unroll
        for (int nt = 0; nt < 4; nt++) {
            const int gcol = bn + wn + nt * 8 + t * 2;
            float b0 = 0.f, b1 = 0.f;
            if (bias) { b0 = __ldg(&bias[gcol]); b1 = __ldg(&bias[gcol + 1]); }
#pragma unroll
            for (int half_ = 0; half_ < 2; half_++) {
                const int grow = bm + wmB + mt * 16 + g + half_ * 8;
                float v0 = acc[mt][nt][half_ * 2 + 0] + b0;
                float v1 = acc[mt][nt][half_ * 2 + 1] + b1;
                if (flags & 1) { v0 = fmaxf(v0, 0.f); v1 = fmaxf(v1, 0.f); }
                const size_t o = (size_t)grow * N + gcol;
                if (flags & 4) {
                    *(float2*)(Cf + o) = make_float2(v0, v1);
                }
                if (flags & 2) {
                    const __half h0 = __float2half_rn(v0);
                    const __half h1 = __float2half_rn(v1);
                    const __half l0 = __float2half_rn(v0 - __half2float(h0));
                    const __half l1 = __float2half_rn(v1 - __half2float(h1));
                    *(__half2*)(Chh + o) = __halves2half2(h0, h1);
                    *(__half2*)(Chl + o) = __halves2half2(l0, l1);
                }
            }
        }
}

// ---------------------------------------------------------------------------
// Transpose + fp16-split weights: W[K,N] -> Wt_hi/lo[N,K]
// ---------------------------------------------------------------------------
__global__ void tsplit_kernel(const float* __restrict__ W, __half* __restrict__ Th,
                              __half* __restrict__ Tl, int Kd, int Nd)
{
    __shared__ float t[32][33];
    const int bx = blockIdx.x * 32;   // N
    const int by = blockIdx.y * 32;   // K
    const int x = threadIdx.x, y0 = threadIdx.y;
#pragma unroll
    for (int dy = 0; dy < 32; dy += 8)
        t[y0 + dy][x] = W[(size_t)(by + y0 + dy) * Nd + bx + x];
    __syncthreads();
#pragma unroll
    for (int dy = 0; dy < 32; dy += 8) {
        const float w = t[x][y0 + dy];
        const __half hi = __float2half_rn(w);
        const __half lo = __float2half_rn(w - __half2float(hi));
        const size_t o = (size_t)(bx + y0 + dy) * Kd + by + x;
        Th[o] = hi;
        Tl[o] = lo;
    }
}

// Elementwise fp16 split (for x).
__global__ void split_kernel(const float* __restrict__ in, __half* __restrict__ hi,
                             __half* __restrict__ lo, int n4)
{
    int i = blockIdx.x * blockDim.x + threadIdx.x;
    if (i >= n4) return;
    float4 a = ((const float4*)in)[i];
    __half h0 = __float2half_rn(a.x), h1 = __float2half_rn(a.y);
    __half h2 = __float2half_rn(a.z), h3 = __float2half_rn(a.w);
    __half l0 = __float2half_rn(a.x - __half2float(h0));
    __half l1 = __float2half_rn(a.y - __half2float(h1));
    __half l2 = __float2half_rn(a.z - __half2float(h2));
    __half l3 = __float2half_rn(a.w - __half2float(h3));
    ((__half2*)hi)[i * 2]     = __halves2half2(h0, h1);
    ((__half2*)hi)[i * 2 + 1] = __halves2half2(h2, h3);
    ((__half2*)lo)[i * 2]     = __halves2half2(l0, l1);
    ((__half2*)lo)[i * 2 + 1] = __halves2half2(l2, l3);
}

// ---------------------------------------------------------------------------
// Neighbor attention (K=8); reads fused qkv[M][3072] = q|k|v.
// ---------------------------------------------------------------------------
__global__ __launch_bounds__(256)
void attn_kernel(const float* __restrict__ qkv, const float* __restrict__ radj,
                 const int* __restrict__ inxs, __half* __restrict__ ch,
                 __half* __restrict__ cl)
{
    const int bt = blockIdx.x;
    const int b = bt >> 10;
    const int tid = threadIdx.x;
    const int wid = tid >> 5, lid = tid & 31;

    __shared__ float s_scores[KNEI];
    __shared__ int s_rows[KNEI];
    if (tid < KNEI) s_rows[tid] = b * TSEQ + inxs[(size_t)bt * KNEI + tid];
    __syncthreads();

    const float4* qv = (const float4*)(qkv + (size_t)bt * QKVLD);
    const float4* kv = (const float4*)(qkv + (size_t)s_rows[wid] * QKVLD + CDIM);
    float sum = 0.f;
#pragma unroll 4
    for (int e = lid; e < CDIM / 4; e += 32) {
        float4 a = qv[e], c = kv[e];
        sum += a.x * c.x + a.y * c.y + a.z * c.z + a.w * c.w;
    }
#pragma unroll
    for (int o = 16; o > 0; o >>= 1) sum += __shfl_xor_sync(0xffffffffu, sum, o);
    if (lid == 0)
        s_scores[wid] = sum * 0.03125f + radj[(size_t)bt * KNEI + wid];
    __syncthreads();

    float w[KNEI];
    float mx = s_scores[0];
#pragma unroll
    for (int j = 1; j < KNEI; j++) mx = fmaxf(mx, s_scores[j]);
    float den = 0.f;
#pragma unroll
    for (int j = 0; j < KNEI; j++) { w[j] = expf(s_scores[j] - mx); den += w[j]; }
    const float inv = 1.f / den;

    float4 o4 = make_float4(0.f, 0.f, 0.f, 0.f);
#pragma unroll
    for (int j = 0; j < KNEI; j++) {
        const float4 v =
            ((const float4*)(qkv + (size_t)s_rows[j] * QKVLD + 2 * CDIM))[tid];
        const float wj = w[j] * inv;
        o4.x = fmaf(wj, v.x, o4.x); o4.y = fmaf(wj, v.y, o4.y);
        o4.z = fmaf(wj, v.z, o4.z); o4.w = fmaf(wj, v.w, o4.w);
    }
    __half h0 = __float2half_rn(o4.x), h1 = __float2half_rn(o4.y);
    __half h2 = __float2half_rn(o4.z), h3 = __float2half_rn(o4.w);
    __half l0 = __float2half_rn(o4.x - __half2float(h0));
    __half l1 = __float2half_rn(o4.y - __half2float(h1));
    __half l2 = __float2half_rn(o4.z - __half2float(h2));
    __half l3 = __float2half_rn(o4.w - __half2float(h3));
    const size_t base2 = (size_t)bt * (CDIM / 2) + tid * 2;
    ((__half2*)ch)[base2]     = __halves2half2(h0, h1);
    ((__half2*)ch)[base2 + 1] = __halves2half2(h2, h3);
    ((__half2*)cl)[base2]     = __halves2half2(l0, l1);
    ((__half2*)cl)[base2 + 1] = __halves2half2(l2, l3);
}

// ---------------------------------------------------------------------------
// Fused residual (+optional relu) LayerNorm; optional fp16-split extra output.
// ---------------------------------------------------------------------------
__global__ __launch_bounds__(256)
void ln_kernel(const float* __restrict__ a, const float* __restrict__ hb,
               const float* __restrict__ g, const float* __restrict__ beta,
               float* __restrict__ out, __half* __restrict__ oh,
               __half* __restrict__ ol, int relu_h)
{
    __shared__ float sh1[8], sh2[8];
    const int bt = blockIdx.x;
    const int tid = threadIdx.x;
    const int wid = tid >> 5, lid = tid & 31;
    const size_t base = (size_t)bt * CDIM;

    float4 z = ((const float4*)(a + base))[tid];
    float4 hh = ((const float4*)(hb + base))[tid];
    if (relu_h) {
        hh.x = fmaxf(hh.x, 0.f); hh.y = fmaxf(hh.y, 0.f);
        hh.z = fmaxf(hh.z, 0.f); hh.w = fmaxf(hh.w, 0.f);
    }
    z.x += hh.x; z.y += hh.y; z.z += hh.z; z.w += hh.w;

    float s = z.x + z.y + z.z + z.w;
    float ss = z.x * z.x + z.y * z.y + z.z * z.z + z.w * z.w;
#pragma unroll
    for (int o = 16; o > 0; o >>= 1) {
        s += __shfl_xor_sync(0xffffffffu, s, o);
        ss += __shfl_xor_sync(0xffffffffu, ss, o);
    }
    if (lid == 0) { sh1[wid] = s; sh2[wid] = ss; }
    __syncthreads();
    float ts = 0.f, tss = 0.f;
#pragma unroll
    for (int j = 0; j < 8; j++) { ts += sh1[j]; tss += sh2[j]; }

    const float mean = ts * (1.f / CDIM);
    const float var = tss * (1.f / CDIM) - mean * mean;
    const float rstd = rsqrtf(var + 1e-5f);

    const float4 gg = ((const float4*)g)[tid];
    const float4 bb = ((const float4*)beta)[tid];
    float4 o4;
    o4.x = (z.x - mean) * rstd * gg.x + bb.x;
    o4.y = (z.y - mean) * rstd * gg.y + bb.y;
    o4.z = (z.z - mean) * rstd * gg.z + bb.z;
    o4.w = (z.w - mean) * rstd * gg.w + bb.w;
    ((float4*)(out + base))[tid] = o4;
    if (oh) {
        __half h0 = __float2half_rn(o4.x), h1 = __float2half_rn(o4.y);
        __half h2 = __float2half_rn(o4.z), h3 = __float2half_rn(o4.w);
        __half l0 = __float2half_rn(o4.x - __half2float(h0));
        __half l1 = __float2half_rn(o4.y - __half2float(h1));
        __half l2 = __float2half_rn(o4.z - __half2float(h2));
        __half l3 = __float2half_rn(o4.w - __half2float(h3));
        const size_t b2 = (size_t)bt * (CDIM / 2) + tid * 2;
        ((__half2*)oh)[b2]     = __halves2half2(h0, h1);
        ((__half2*)oh)[b2 + 1] = __halves2half2(h2, h3);
        ((__half2*)ol)[b2]     = __halves2half2(l0, l1);
        ((__half2*)ol)[b2 + 1] = __halves2half2(l2, l3);
    }
}

// ---------------------------------------------------------------------------
// Launch
// ---------------------------------------------------------------------------
extern "C" void kernel_launch(void* const* d_in, const int* in_sizes, int n_in,
                              void* d_out, int out_size)
{
    const float* x    = (const float*)d_in[0];
    const float* radj = (const float*)d_in[1];
    const int*   inxs = (const int*)  d_in[2];
    const float* Wq   = (const float*)d_in[3];
    const float* Wk   = (const float*)d_in[4];
    const float* Wv   = (const float*)d_in[5];
    const float* Wo   = (const float*)d_in[6];
    const float* ln1g = (const float*)d_in[7];
    const float* ln1b = (const float*)d_in[8];
    const float* W1   = (const float*)d_in[9];
    const float* b1   = (const float*)d_in[10];
    const float* W2   = (const float*)d_in[11];
    const float* b2   = (const float*)d_in[12];
    const float* ln2g = (const float*)d_in[13];
    const float* ln2b = (const float*)d_in[14];
    float* out = (float*)d_out;

    float *qkv, *h32, *y, *f;
    __half *ctxh, *ctxl, *hh, *hl, *yh, *yl, *xh, *xl, *hidh, *hidl;
    __half *wqkvh, *wqkvl, *woh, *wol, *w1h, *w1l, *w2h, *w2l;
    cudaGetSymbolAddress((void**)&qkv, g_qkv);
    cudaGetSymbolAddress((void**)&ctxh, g_ctxh); cudaGetSymbolAddress((void**)&ctxl, g_ctxl);
    cudaGetSymbolAddress((void**)&hh, g_hh);     cudaGetSymbolAddress((void**)&hl, g_hl);
    cudaGetSymbolAddress((void**)&h32, g_h32);   cudaGetSymbolAddress((void**)&y, g_y);
    cudaGetSymbolAddress((void**)&yh, g_yh);     cudaGetSymbolAddress((void**)&yl, g_yl);
    cudaGetSymbolAddress((void**)&f, g_f);       cudaGetSymbolAddress((void**)&xh, g_xh);
    cudaGetSymbolAddress((void**)&xl, g_xl);     cudaGetSymbolAddress((void**)&hidh, g_hidh);
    cudaGetSymbolAddress((void**)&hidl, g_hidl);
    cudaGetSymbolAddress((void**)&wqkvh, g_wqkvh); cudaGetSymbolAddress((void**)&wqkvl, g_wqkvl);
    cudaGetSymbolAddress((void**)&woh, g_woh);   cudaGetSymbolAddress((void**)&wol, g_wol);
    cudaGetSymbolAddress((void**)&w1h, g_w1h);   cudaGetSymbolAddress((void**)&w1l, g_w1l);
    cudaGetSymbolAddress((void**)&w2h, g_w2h);   cudaGetSymbolAddress((void**)&w2l, g_w2l);

    cudaFuncSetAttribute(mm_fp16x2_kernel,
                         cudaFuncAttributeMaxDynamicSharedMemorySize, MM_SMEM);

    const dim3 b256(256);
    const dim3 tblk(32, 8);

    // Weight transpose + split. QKV stacked: rows 0-1023 Wq, 1024-2047 Wk, 2048-3071 Wv.
    tsplit_kernel<<<dim3(CDIM / 32, CDIM / 32), tblk>>>(Wq, wqkvh, wqkvl, CDIM, CDIM);
    tsplit_kernel<<<dim3(CDIM / 32, CDIM / 32), tblk>>>(
        Wk, wqkvh + (size_t)CDIM * CDIM, wqkvl + (size_t)CDIM * CDIM, CDIM, CDIM);
    tsplit_kernel<<<dim3(CDIM / 32, CDIM / 32), tblk>>>(
        Wv, wqkvh + (size_t)2 * CDIM * CDIM, wqkvl + (size_t)2 * CDIM * CDIM, CDIM, CDIM);
    tsplit_kernel<<<dim3(CDIM / 32, CDIM / 32), tblk>>>(Wo, woh, wol, CDIM, CDIM);
    tsplit_kernel<<<dim3(HDIM / 32, CDIM / 32), tblk>>>(W1, w1h, w1l, CDIM, HDIM);
    tsplit_kernel<<<dim3(CDIM / 32, HDIM / 32), tblk>>>(W2, w2h, w2l, HDIM, CDIM);
    split_kernel<<<(MDIM * CDIM / 4 + 255) / 256, b256>>>(x, xh, xl, MDIM * CDIM / 4);

    const dim3 gQKV(QKVLD / 128, MDIM / 128);  // (24, 128)
    const dim3 gCC(CDIM / 128, MDIM / 128);    // (8, 128)
    const dim3 gCH(HDIM / 128, MDIM / 128);    // (12, 128)

    const __half *ah = xh, *al = xl;
    for (int hop = 0; hop < 2; hop++) {
        // fused q|k|v = A @ Wqkv^T
        mm_fp16x2_kernel<<<gQKV, 256, MM_SMEM>>>(ah, al, wqkvh, wqkvl, qkv, nullptr,
                                                 nullptr, nullptr, QKVLD, CDIM, 4);
        attn_kernel<<<MDIM, b256>>>(qkv, radj, inxs, ctxh, ctxl);
        if (hop == 0) {
            mm_fp16x2_kernel<<<gCC, 256, MM_SMEM>>>(ctxh, ctxl, woh, wol, nullptr, hh, hl,
                                                    nullptr, CDIM, CDIM, 2);
            ah = hh; al = hl;
        } else {
            mm_fp16x2_kernel<<<gCC, 256, MM_SMEM>>>(ctxh, ctxl, woh, wol, h32, nullptr,
                                                    nullptr, nullptr, CDIM, CDIM, 4);
        }
    }

    // y = LN(x + relu(h));  + fp16 split for FFN input
    ln_kernel<<<MDIM, b256>>>(x, h32, ln1g, ln1b, y, yh, yl, 1);
    // hid = relu(y @ W1 + b1)  -> fp16 split
    mm_fp16x2_kernel<<<gCH, 256, MM_SMEM>>>(yh, yl, w1h, w1l, nullptr, hidh, hidl,
                                            b1, HDIM, CDIM, 1 | 2);
    // f = hid @ W2 + b2  -> fp32
    mm_fp16x2_kernel<<<gCC, 256, MM_SMEM>>>(hidh, hidl, w2h, w2l, f, nullptr, nullptr,
                                            b2, CDIM, HDIM, 4);
    // out = LN(y + f)
    ln_kernel<<<MDIM, b256>>>(y, f, ln2g, ln2b, out, nullptr, nullptr, 0);
}

// round 5
// speedup vs baseline: 1.4425x; 1.4425x over previous
#include <cuda_runtime.h>
#include <cuda_fp16.h>
#include <cstdint>
#include <math.h>

// ============================================================================
// ReasonNet via ldmatrix + mma.sync (HMMA).
// Round 5: 2-term split GEMM — A = Ah+Al (fp16 pair, exact), B = fp16 single.
//   C = (Ah+Al) @ Bh^T  => only error is B's fp16 rounding (~1.4e-4 rel).
// MMA count = 2/3 of round 3.  BK=32, 3-stage cp.async (round-3 pipeline).
// B=16, T=1024, C=1024, K=8, H=1536.  M = B*T = 16384.
// ============================================================================

#define MDIM 16384
#define CDIM 1024
#define HDIM 1536
#define KNEI 8
#define TSEQ 1024
#define QKVLD 3072

#define BK 32
#define KSTRIDE 40                  // halfs per smem row (80B: aligned + LDSM conflict-free)
#define ROWB 80
#define STG_A_H 0
#define STG_A_L 10240               // 128*80
#define STG_B_H 20480
#define STG_BYTES 30720
#define MM_SMEM (3 * STG_BYTES)     // 92160 bytes

// ---------------------------------------------------------------------------
// Scratch (static device globals; runtime allocation forbidden).
// ---------------------------------------------------------------------------
__device__ float  g_qkv [(size_t)MDIM * QKVLD];   // fused q|k|v per hop
__device__ __half g_ctxh[(size_t)MDIM * CDIM];
__device__ __half g_ctxl[(size_t)MDIM * CDIM];
__device__ __half g_hh  [(size_t)MDIM * CDIM];
__device__ __half g_hl  [(size_t)MDIM * CDIM];
__device__ float  g_h32 [(size_t)MDIM * CDIM];
__device__ float  g_y   [(size_t)MDIM * CDIM];
__device__ __half g_yh  [(size_t)MDIM * CDIM];
__device__ __half g_yl  [(size_t)MDIM * CDIM];
__device__ float  g_f   [(size_t)MDIM * CDIM];
__device__ __half g_xh  [(size_t)MDIM * CDIM];
__device__ __half g_xl  [(size_t)MDIM * CDIM];
__device__ __half g_hidh[(size_t)MDIM * HDIM];
__device__ __half g_hidl[(size_t)MDIM * HDIM];
// Transposed fp16 weights: Wt[N][K].  QKV stacked (3072 rows).
__device__ __half g_wqkvh[(size_t)QKVLD * CDIM];
__device__ __half g_woh[(size_t)CDIM * CDIM];
__device__ __half g_w1h[(size_t)HDIM * CDIM];
__device__ __half g_w2h[(size_t)CDIM * HDIM];

// ---------------------------------------------------------------------------
// PTX helpers (sm_80-portable only)
// ---------------------------------------------------------------------------
__device__ __forceinline__ uint32_t smem_u32(const void* p) {
    uint32_t a;
    asm("{ .reg .u64 t; cvta.to.shared.u64 t, %1; cvt.u32.u64 %0, t; }"
        : "=r"(a) : "l"(p));
    return a;
}
__device__ __forceinline__ void cp16(uint32_t s, const void* g) {
    asm volatile("cp.async.cg.shared.global [%0], [%1], 16;" :: "r"(s), "l"(g) : "memory");
}
__device__ __forceinline__ void ldsm4(uint32_t* r, uint32_t addr) {
    asm volatile("ldmatrix.sync.aligned.m8n8.x4.shared.b16 {%0,%1,%2,%3}, [%4];"
                 : "=r"(r[0]), "=r"(r[1]), "=r"(r[2]), "=r"(r[3]) : "r"(addr));
}
__device__ __forceinline__ void mma16816(float* c, const uint32_t* a, const uint32_t* b) {
    asm volatile(
        "mma.sync.aligned.m16n8k16.row.col.f32.f16.f16.f32 "
        "{%0,%1,%2,%3}, {%4,%5,%6,%7}, {%8,%9}, {%0,%1,%2,%3};"
        : "+f"(c[0]), "+f"(c[1]), "+f"(c[2]), "+f"(c[3])
        : "r"(a[0]), "r"(a[1]), "r"(a[2]), "r"(a[3]), "r"(b[0]), "r"(b[1]));
}

// ---------------------------------------------------------------------------
// 2-term GEMM: C[M,N] = (Ah+Al)[M,K] @ Bh[N,K]^T
// flags: bit0 relu, bit1 write fp16 split (Chh/Chl), bit2 write fp32 (Cf).
// 256 threads, 128x128 tile, BK=32, 3-stage cp.async pipeline.
// ---------------------------------------------------------------------------
__global__ __launch_bounds__(256, 1)
void mm_fp16x2_kernel(const __half* __restrict__ Ah, const __half* __restrict__ Al,
                      const __half* __restrict__ Bh,
                      float* __restrict__ Cf, __half* __restrict__ Chh,
                      __half* __restrict__ Chl, const float* __restrict__ bias,
                      int N, int K, int flags)
{
    extern __shared__ char smem[];
    const uint32_t sb = smem_u32(smem);
    const int tid  = threadIdx.x;
    const int wid  = tid >> 5;
    const int lane = tid & 31;
    const int bm   = blockIdx.y * 128;
    const int bn   = blockIdx.x * 128;
    const int wmB  = (wid >> 2) * 64;
    const int wn   = (wid & 3) * 32;
    const int ntiles = K / BK;

    // -------- producer addressing --------
    const int row = tid & 127;
    const int sg0 = tid >> 7;           // 0/1; covers segs sg0, sg0+2
    const __half* gAh = Ah + (size_t)(bm + row) * K;
    const __half* gAl = Al + (size_t)(bm + row) * K;
    const __half* gBh = Bh + (size_t)(bn + row) * K;
    const uint32_t doff = (uint32_t)row * ROWB;

    auto issue = [&](int kt, int s) {
        const uint32_t st = sb + (uint32_t)s * STG_BYTES;
        const size_t kof = (size_t)kt * BK;
#pragma unroll
        for (int qq = 0; qq < 2; qq++) {
            const int seg = sg0 + qq * 2;
            const uint32_t d = doff + seg * 16;
            const size_t g = kof + seg * 8;
            cp16(st + STG_A_H + d, gAh + g);
            cp16(st + STG_A_L + d, gAl + g);
            cp16(st + STG_B_H + d, gBh + g);
        }
        asm volatile("cp.async.commit_group;" ::: "memory");
    };

    float acc[4][4][4];
#pragma unroll
    for (int i = 0; i < 4; i++)
#pragma unroll
        for (int j = 0; j < 4; j++)
#pragma unroll
            for (int l = 0; l < 4; l++) acc[i][j][l] = 0.f;

    issue(0, 0);
    issue(1, 1);

    // ldmatrix lane addressing
    const int arow  = lane & 15;
    const int acol8 = (lane >> 4) * 8;
    const int brow  = (lane & 7) + ((lane >> 4) << 3);
    const int bcol8 = ((lane >> 3) & 1) * 8;

    for (int kt = 0; kt < ntiles; kt++) {
        if (kt == ntiles - 1)
            asm volatile("cp.async.wait_group 0;" ::: "memory");
        else
            asm volatile("cp.async.wait_group 1;" ::: "memory");
        __syncthreads();

        const uint32_t stg = sb + (uint32_t)(kt % 3) * STG_BYTES;
#pragma unroll
        for (int ks = 0; ks < 2; ks++) {
            const int kb = ks * 16;
            uint32_t ahf[4][4], alf[4][4], bhf[2][4];
#pragma unroll
            for (int mt = 0; mt < 4; mt++) {
                const uint32_t off =
                    (uint32_t)((wmB + mt * 16 + arow) * KSTRIDE + kb + acol8) * 2;
                ldsm4(ahf[mt], stg + STG_A_H + off);
                ldsm4(alf[mt], stg + STG_A_L + off);
            }
#pragma unroll
            for (int nt2 = 0; nt2 < 2; nt2++) {
                const uint32_t off =
                    (uint32_t)((wn + nt2 * 16 + brow) * KSTRIDE + kb + bcol8) * 2;
                ldsm4(bhf[nt2], stg + STG_B_H + off);
            }
#pragma unroll
            for (int mt = 0; mt < 4; mt++)
#pragma unroll
                for (int nt = 0; nt < 4; nt++) {
                    const uint32_t* bh = &bhf[nt >> 1][(nt & 1) * 2];
                    mma16816(acc[mt][nt], ahf[mt], bh);   // hi * B
                    mma16816(acc[mt][nt], alf[mt], bh);   // lo * B
                }
        }
        if (kt + 2 < ntiles) issue(kt + 2, (kt + 2) % 3);
    }

    // -------- epilogue --------
    const int g = lane >> 2;
    const int t = lane & 3;
#pragma unroll
    for (int mt = 0; mt < 4; mt++)
#pragma unroll
        for (int nt = 0; nt < 4; nt++) {
            const int gcol = bn + wn + nt * 8 + t * 2;
            float b0 = 0.f, b1 = 0.f;
            if (bias) { b0 = __ldg(&bias[gcol]); b1 = __ldg(&bias[gcol + 1]); }
#pragma unroll
            for (int half_ = 0; half_ < 2; half_++) {
                const int grow = bm + wmB + mt * 16 + g + half_ * 8;
                float v0 = acc[mt][nt][half_ * 2 + 0] + b0;
                float v1 = acc[mt][nt][half_ * 2 + 1] + b1;
                if (flags & 1) { v0 = fmaxf(v0, 0.f); v1 = fmaxf(v1, 0.f); }
                const size_t o = (size_t)grow * N + gcol;
                if (flags & 4) {
                    *(float2*)(Cf + o) = make_float2(v0, v1);
                }
                if (flags & 2) {
                    const __half h0 = __float2half_rn(v0);
                    const __half h1 = __float2half_rn(v1);
                    const __half l0 = __float2half_rn(v0 - __half2float(h0));
                    const __half l1 = __float2half_rn(v1 - __half2float(h1));
                    *(__half2*)(Chh + o) = __halves2half2(h0, h1);
                    *(__half2*)(Chl + o) = __halves2half2(l0, l1);
                }
            }
        }
}

// ---------------------------------------------------------------------------
// Transpose + round weights to fp16: W[K,N] -> Wt[N,K]
// ---------------------------------------------------------------------------
__global__ void thalf_kernel(const float* __restrict__ W, __half* __restrict__ Th,
                             int Kd, int Nd)
{
    __shared__ float t[32][33];
    const int bx = blockIdx.x * 32;   // N
    const int by = blockIdx.y * 32;   // K
    const int x = threadIdx.x, y0 = threadIdx.y;
#pragma unroll
    for (int dy = 0; dy < 32; dy += 8)
        t[y0 + dy][x] = W[(size_t)(by + y0 + dy) * Nd + bx + x];
    __syncthreads();
#pragma unroll
    for (int dy = 0; dy < 32; dy += 8) {
        const float w = t[x][y0 + dy];
        Th[(size_t)(bx + y0 + dy) * Kd + by + x] = __float2half_rn(w);
    }
}

// Elementwise fp16 split (for x).
__global__ void split_kernel(const float* __restrict__ in, __half* __restrict__ hi,
                             __half* __restrict__ lo, int n4)
{
    int i = blockIdx.x * blockDim.x + threadIdx.x;
    if (i >= n4) return;
    float4 a = ((const float4*)in)[i];
    __half h0 = __float2half_rn(a.x), h1 = __float2half_rn(a.y);
    __half h2 = __float2half_rn(a.z), h3 = __float2half_rn(a.w);
    __half l0 = __float2half_rn(a.x - __half2float(h0));
    __half l1 = __float2half_rn(a.y - __half2float(h1));
    __half l2 = __float2half_rn(a.z - __half2float(h2));
    __half l3 = __float2half_rn(a.w - __half2float(h3));
    ((__half2*)hi)[i * 2]     = __halves2half2(h0, h1);
    ((__half2*)hi)[i * 2 + 1] = __halves2half2(h2, h3);
    ((__half2*)lo)[i * 2]     = __halves2half2(l0, l1);
    ((__half2*)lo)[i * 2 + 1] = __halves2half2(l2, l3);
}

// ---------------------------------------------------------------------------
// Neighbor attention (K=8); reads fused qkv[M][3072] = q|k|v.
// ---------------------------------------------------------------------------
__global__ __launch_bounds__(256)
void attn_kernel(const float* __restrict__ qkv, const float* __restrict__ radj,
                 const int* __restrict__ inxs, __half* __restrict__ ch,
                 __half* __restrict__ cl)
{
    const int bt = blockIdx.x;
    const int b = bt >> 10;
    const int tid = threadIdx.x;
    const int wid = tid >> 5, lid = tid & 31;

    __shared__ float s_scores[KNEI];
    __shared__ int s_rows[KNEI];
    if (tid < KNEI) s_rows[tid] = b * TSEQ + inxs[(size_t)bt * KNEI + tid];
    __syncthreads();

    const float4* qv = (const float4*)(qkv + (size_t)bt * QKVLD);
    const float4* kv = (const float4*)(qkv + (size_t)s_rows[wid] * QKVLD + CDIM);
    float sum = 0.f;
#pragma unroll 4
    for (int e = lid; e < CDIM / 4; e += 32) {
        float4 a = qv[e], c = kv[e];
        sum += a.x * c.x + a.y * c.y + a.z * c.z + a.w * c.w;
    }
#pragma unroll
    for (int o = 16; o > 0; o >>= 1) sum += __shfl_xor_sync(0xffffffffu, sum, o);
    if (lid == 0)
        s_scores[wid] = sum * 0.03125f + radj[(size_t)bt * KNEI + wid];
    __syncthreads();

    float w[KNEI];
    float mx = s_scores[0];
#pragma unroll
    for (int j = 1; j < KNEI; j++) mx = fmaxf(mx, s_scores[j]);
    float den = 0.f;
#pragma unroll
    for (int j = 0; j < KNEI; j++) { w[j] = expf(s_scores[j] - mx); den += w[j]; }
    const float inv = 1.f / den;

    float4 o4 = make_float4(0.f, 0.f, 0.f, 0.f);
#pragma unroll
    for (int j = 0; j < KNEI; j++) {
        const float4 v =
            ((const float4*)(qkv + (size_t)s_rows[j] * QKVLD + 2 * CDIM))[tid];
        const float wj = w[j] * inv;
        o4.x = fmaf(wj, v.x, o4.x); o4.y = fmaf(wj, v.y, o4.y);
        o4.z = fmaf(wj, v.z, o4.z); o4.w = fmaf(wj, v.w, o4.w);
    }
    __half h0 = __float2half_rn(o4.x), h1 = __float2half_rn(o4.y);
    __half h2 = __float2half_rn(o4.z), h3 = __float2half_rn(o4.w);
    __half l0 = __float2half_rn(o4.x - __half2float(h0));
    __half l1 = __float2half_rn(o4.y - __half2float(h1));
    __half l2 = __float2half_rn(o4.z - __half2float(h2));
    __half l3 = __float2half_rn(o4.w - __half2float(h3));
    const size_t base2 = (size_t)bt * (CDIM / 2) + tid * 2;
    ((__half2*)ch)[base2]     = __halves2half2(h0, h1);
    ((__half2*)ch)[base2 + 1] = __halves2half2(h2, h3);
    ((__half2*)cl)[base2]     = __halves2half2(l0, l1);
    ((__half2*)cl)[base2 + 1] = __halves2half2(l2, l3);
}

// ---------------------------------------------------------------------------
// Fused residual (+optional relu) LayerNorm; optional fp16-split extra output.
// ---------------------------------------------------------------------------
__global__ __launch_bounds__(256)
void ln_kernel(const float* __restrict__ a, const float* __restrict__ hb,
               const float* __restrict__ g, const float* __restrict__ beta,
               float* __restrict__ out, __half* __restrict__ oh,
               __half* __restrict__ ol, int relu_h)
{
    __shared__ float sh1[8], sh2[8];
    const int bt = blockIdx.x;
    const int tid = threadIdx.x;
    const int wid = tid >> 5, lid = tid & 31;
    const size_t base = (size_t)bt * CDIM;

    float4 z = ((const float4*)(a + base))[tid];
    float4 hh = ((const float4*)(hb + base))[tid];
    if (relu_h) {
        hh.x = fmaxf(hh.x, 0.f); hh.y = fmaxf(hh.y, 0.f);
        hh.z = fmaxf(hh.z, 0.f); hh.w = fmaxf(hh.w, 0.f);
    }
    z.x += hh.x; z.y += hh.y; z.z += hh.z; z.w += hh.w;

    float s = z.x + z.y + z.z + z.w;
    float ss = z.x * z.x + z.y * z.y + z.z * z.z + z.w * z.w;
#pragma unroll
    for (int o = 16; o > 0; o >>= 1) {
        s += __shfl_xor_sync(0xffffffffu, s, o);
        ss += __shfl_xor_sync(0xffffffffu, ss, o);
    }
    if (lid == 0) { sh1[wid] = s; sh2[wid] = ss; }
    __syncthreads();
    float ts = 0.f, tss = 0.f;
#pragma unroll
    for (int j = 0; j < 8; j++) { ts += sh1[j]; tss += sh2[j]; }

    const float mean = ts * (1.f / CDIM);
    const float var = tss * (1.f / CDIM) - mean * mean;
    const float rstd = rsqrtf(var + 1e-5f);

    const float4 gg = ((const float4*)g)[tid];
    const float4 bb = ((const float4*)beta)[tid];
    float4 o4;
    o4.x = (z.x - mean) * rstd * gg.x + bb.x;
    o4.y = (z.y - mean) * rstd * gg.y + bb.y;
    o4.z = (z.z - mean) * rstd * gg.z + bb.z;
    o4.w = (z.w - mean) * rstd * gg.w + bb.w;
    ((float4*)(out + base))[tid] = o4;
    if (oh) {
        __half h0 = __float2half_rn(o4.x), h1 = __float2half_rn(o4.y);
        __half h2 = __float2half_rn(o4.z), h3 = __float2half_rn(o4.w);
        __half l0 = __float2half_rn(o4.x - __half2float(h0));
        __half l1 = __float2half_rn(o4.y - __half2float(h1));
        __half l2 = __float2half_rn(o4.z - __half2float(h2));
        __half l3 = __float2half_rn(o4.w - __half2float(h3));
        const size_t b2 = (size_t)bt * (CDIM / 2) + tid * 2;
        ((__half2*)oh)[b2]     = __halves2half2(h0, h1);
        ((__half2*)oh)[b2 + 1] = __halves2half2(h2, h3);
        ((__half2*)ol)[b2]     = __halves2half2(l0, l1);
        ((__half2*)ol)[b2 + 1] = __halves2half2(l2, l3);
    }
}

// ---------------------------------------------------------------------------
// Launch
// ---------------------------------------------------------------------------
extern "C" void kernel_launch(void* const* d_in, const int* in_sizes, int n_in,
                              void* d_out, int out_size)
{
    const float* x    = (const float*)d_in[0];
    const float* radj = (const float*)d_in[1];
    const int*   inxs = (const int*)  d_in[2];
    const float* Wq   = (const float*)d_in[3];
    const float* Wk   = (const float*)d_in[4];
    const float* Wv   = (const float*)d_in[5];
    const float* Wo   = (const float*)d_in[6];
    const float* ln1g = (const float*)d_in[7];
    const float* ln1b = (const float*)d_in[8];
    const float* W1   = (const float*)d_in[9];
    const float* b1   = (const float*)d_in[10];
    const float* W2   = (const float*)d_in[11];
    const float* b2   = (const float*)d_in[12];
    const float* ln2g = (const float*)d_in[13];
    const float* ln2b = (const float*)d_in[14];
    float* out = (float*)d_out;

    float *qkv, *h32, *y, *f;
    __half *ctxh, *ctxl, *hh, *hl, *yh, *yl, *xh, *xl, *hidh, *hidl;
    __half *wqkvh, *woh, *w1h, *w2h;
    cudaGetSymbolAddress((void**)&qkv, g_qkv);
    cudaGetSymbolAddress((void**)&ctxh, g_ctxh); cudaGetSymbolAddress((void**)&ctxl, g_ctxl);
    cudaGetSymbolAddress((void**)&hh, g_hh);     cudaGetSymbolAddress((void**)&hl, g_hl);
    cudaGetSymbolAddress((void**)&h32, g_h32);   cudaGetSymbolAddress((void**)&y, g_y);
    cudaGetSymbolAddress((void**)&yh, g_yh);     cudaGetSymbolAddress((void**)&yl, g_yl);
    cudaGetSymbolAddress((void**)&f, g_f);       cudaGetSymbolAddress((void**)&xh, g_xh);
    cudaGetSymbolAddress((void**)&xl, g_xl);     cudaGetSymbolAddress((void**)&hidh, g_hidh);
    cudaGetSymbolAddress((void**)&hidl, g_hidl);
    cudaGetSymbolAddress((void**)&wqkvh, g_wqkvh);
    cudaGetSymbolAddress((void**)&woh, g_woh);
    cudaGetSymbolAddress((void**)&w1h, g_w1h);
    cudaGetSymbolAddress((void**)&w2h, g_w2h);

    cudaFuncSetAttribute(mm_fp16x2_kernel,
                         cudaFuncAttributeMaxDynamicSharedMemorySize, MM_SMEM);

    const dim3 b256(256);
    const dim3 tblk(32, 8);

    // Weight transpose (fp16).  QKV stacked: rows 0-1023 Wq, 1024-2047 Wk, 2048-3071 Wv.
    thalf_kernel<<<dim3(CDIM / 32, CDIM / 32), tblk>>>(Wq, wqkvh, CDIM, CDIM);
    thalf_kernel<<<dim3(CDIM / 32, CDIM / 32), tblk>>>(Wk, wqkvh + (size_t)CDIM * CDIM, CDIM, CDIM);
    thalf_kernel<<<dim3(CDIM / 32, CDIM / 32), tblk>>>(Wv, wqkvh + (size_t)2 * CDIM * CDIM, CDIM, CDIM);
    thalf_kernel<<<dim3(CDIM / 32, CDIM / 32), tblk>>>(Wo, woh, CDIM, CDIM);
    thalf_kernel<<<dim3(HDIM / 32, CDIM / 32), tblk>>>(W1, w1h, CDIM, HDIM);
    thalf_kernel<<<dim3(CDIM / 32, HDIM / 32), tblk>>>(W2, w2h, HDIM, CDIM);
    split_kernel<<<(MDIM * CDIM / 4 + 255) / 256, b256>>>(x, xh, xl, MDIM * CDIM / 4);

    const dim3 gQKV(QKVLD / 128, MDIM / 128);  // (24, 128)
    const dim3 gCC(CDIM / 128, MDIM / 128);    // (8, 128)
    const dim3 gCH(HDIM / 128, MDIM / 128);    // (12, 128)

    const __half *ah = xh, *al = xl;
    for (int hop = 0; hop < 2; hop++) {
        // fused q|k|v = A @ Wqkv^T
        mm_fp16x2_kernel<<<gQKV, 256, MM_SMEM>>>(ah, al, wqkvh, qkv, nullptr,
                                                 nullptr, nullptr, QKVLD, CDIM, 4);
        attn_kernel<<<MDIM, b256>>>(qkv, radj, inxs, ctxh, ctxl);
        if (hop == 0) {
            mm_fp16x2_kernel<<<gCC, 256, MM_SMEM>>>(ctxh, ctxl, woh, nullptr, hh, hl,
                                                    nullptr, CDIM, CDIM, 2);
            ah = hh; al = hl;
        } else {
            mm_fp16x2_kernel<<<gCC, 256, MM_SMEM>>>(ctxh, ctxl, woh, h32, nullptr,
                                                    nullptr, nullptr, CDIM, CDIM, 4);
        }
    }

    // y = LN(x + relu(h));  + fp16 split for FFN input
    ln_kernel<<<MDIM, b256>>>(x, h32, ln1g, ln1b, y, yh, yl, 1);
    // hid = relu(y @ W1 + b1)  -> fp16 split
    mm_fp16x2_kernel<<<gCH, 256, MM_SMEM>>>(yh, yl, w1h, nullptr, hidh, hidl,
                                            b1, HDIM, CDIM, 1 | 2);
    // f = hid @ W2 + b2  -> fp32
    mm_fp16x2_kernel<<<gCC, 256, MM_SMEM>>>(hidh, hidl, w2h, f, nullptr, nullptr,
                                            b2, CDIM, HDIM, 4);
    // out = LN(y + f)
    ln_kernel<<<MDIM, b256>>>(y, f, ln2g, ln2b, out, nullptr, nullptr, 0);
}

// round 6
// speedup vs baseline: 2.3381x; 1.6208x over previous
#include <cuda_runtime.h>
#include <cuda_fp16.h>
#include <cstdint>
#include <math.h>

// ============================================================================
// ReasonNet via ldmatrix + mma.sync (HMMA).
// Round 6: pure fp16 GEMM (1 MMA/fragment).  A,B rounded to fp16; fp32 accum.
// Measured error model: B-only rounding gave 1.8e-4; A+B predicted ~2.5-4e-4,
// threshold 1e-3.  MMA count = 1/2 of round 5.
// B=16, T=1024, C=1024, K=8, H=1536.  M = B*T = 16384.
// ============================================================================

#define MDIM 16384
#define CDIM 1024
#define HDIM 1536
#define KNEI 8
#define TSEQ 1024
#define QKVLD 3072

#define BK 32
#define KSTRIDE 40                  // halfs per smem row (80B: aligned + LDSM conflict-free)
#define ROWB 80
#define STG_A 0
#define STG_B 10240                 // 128*80
#define STG_BYTES 20480
#define MM_SMEM (3 * STG_BYTES)     // 61440 bytes

// ---------------------------------------------------------------------------
// Scratch (static device globals; runtime allocation forbidden).
// ---------------------------------------------------------------------------
__device__ float  g_qkv [(size_t)MDIM * QKVLD];   // fused q|k|v per hop (fp32)
__device__ __half g_ctx [(size_t)MDIM * CDIM];
__device__ __half g_h1  [(size_t)MDIM * CDIM];
__device__ float  g_h32 [(size_t)MDIM * CDIM];
__device__ float  g_y   [(size_t)MDIM * CDIM];
__device__ __half g_yh  [(size_t)MDIM * CDIM];
__device__ float  g_f   [(size_t)MDIM * CDIM];
__device__ __half g_xh  [(size_t)MDIM * CDIM];
__device__ __half g_hid [(size_t)MDIM * HDIM];
// Transposed fp16 weights: Wt[N][K].  QKV stacked (3072 rows).
__device__ __half g_wqkvh[(size_t)QKVLD * CDIM];
__device__ __half g_woh[(size_t)CDIM * CDIM];
__device__ __half g_w1h[(size_t)HDIM * CDIM];
__device__ __half g_w2h[(size_t)CDIM * HDIM];

// ---------------------------------------------------------------------------
// PTX helpers (sm_80-portable only)
// ---------------------------------------------------------------------------
__device__ __forceinline__ uint32_t smem_u32(const void* p) {
    uint32_t a;
    asm("{ .reg .u64 t; cvta.to.shared.u64 t, %1; cvt.u32.u64 %0, t; }"
        : "=r"(a) : "l"(p));
    return a;
}
__device__ __forceinline__ void cp16(uint32_t s, const void* g) {
    asm volatile("cp.async.cg.shared.global [%0], [%1], 16;" :: "r"(s), "l"(g) : "memory");
}
__device__ __forceinline__ void ldsm4(uint32_t* r, uint32_t addr) {
    asm volatile("ldmatrix.sync.aligned.m8n8.x4.shared.b16 {%0,%1,%2,%3}, [%4];"
                 : "=r"(r[0]), "=r"(r[1]), "=r"(r[2]), "=r"(r[3]) : "r"(addr));
}
__device__ __forceinline__ void mma16816(float* c, const uint32_t* a, const uint32_t* b) {
    asm volatile(
        "mma.sync.aligned.m16n8k16.row.col.f32.f16.f16.f32 "
        "{%0,%1,%2,%3}, {%4,%5,%6,%7}, {%8,%9}, {%0,%1,%2,%3};"
        : "+f"(c[0]), "+f"(c[1]), "+f"(c[2]), "+f"(c[3])
        : "r"(a[0]), "r"(a[1]), "r"(a[2]), "r"(a[3]), "r"(b[0]), "r"(b[1]));
}

// ---------------------------------------------------------------------------
// fp16 GEMM: C[M,N] = A[M,K] @ B[N,K]^T  (fp32 accumulate)
// flags: bit0 relu, bit1 write fp16 (Ch), bit2 write fp32 (Cf).
// 256 threads, 128x128 tile, BK=32, 3-stage cp.async pipeline.
// ---------------------------------------------------------------------------
__global__ __launch_bounds__(256, 2)
void mm_fp16_kernel(const __half* __restrict__ A, const __half* __restrict__ B,
                    float* __restrict__ Cf, __half* __restrict__ Ch,
                    const float* __restrict__ bias, int N, int K, int flags)
{
    extern __shared__ char smem[];
    const uint32_t sb = smem_u32(smem);
    const int tid  = threadIdx.x;
    const int wid  = tid >> 5;
    const int lane = tid & 31;
    const int bm   = blockIdx.y * 128;
    const int bn   = blockIdx.x * 128;
    const int wmB  = (wid >> 2) * 64;
    const int wn   = (wid & 3) * 32;
    const int ntiles = K / BK;

    // -------- producer addressing --------
    const int row = tid & 127;
    const int sg0 = tid >> 7;           // 0/1; covers segs sg0, sg0+2
    const __half* gA = A + (size_t)(bm + row) * K;
    const __half* gB = B + (size_t)(bn + row) * K;
    const uint32_t doff = (uint32_t)row * ROWB;

    auto issue = [&](int kt, int s) {
        const uint32_t st = sb + (uint32_t)s * STG_BYTES;
        const size_t kof = (size_t)kt * BK;
#pragma unroll
        for (int qq = 0; qq < 2; qq++) {
            const int seg = sg0 + qq * 2;
            const uint32_t d = doff + seg * 16;
            const size_t g = kof + seg * 8;
            cp16(st + STG_A + d, gA + g);
            cp16(st + STG_B + d, gB + g);
        }
        asm volatile("cp.async.commit_group;" ::: "memory");
    };

    float acc[4][4][4];
#pragma unroll
    for (int i = 0; i < 4; i++)
#pragma unroll
        for (int j = 0; j < 4; j++)
#pragma unroll
            for (int l = 0; l < 4; l++) acc[i][j][l] = 0.f;

    issue(0, 0);
    issue(1, 1);

    // ldmatrix lane addressing
    const int arow  = lane & 15;
    const int acol8 = (lane >> 4) * 8;
    const int brow  = (lane & 7) + ((lane >> 4) << 3);
    const int bcol8 = ((lane >> 3) & 1) * 8;

    for (int kt = 0; kt < ntiles; kt++) {
        if (kt == ntiles - 1)
            asm volatile("cp.async.wait_group 0;" ::: "memory");
        else
            asm volatile("cp.async.wait_group 1;" ::: "memory");
        __syncthreads();

        const uint32_t stg = sb + (uint32_t)(kt % 3) * STG_BYTES;
#pragma unroll
        for (int ks = 0; ks < 2; ks++) {
            const int kb = ks * 16;
            uint32_t af[4][4], bf[2][4];
#pragma unroll
            for (int mt = 0; mt < 4; mt++) {
                const uint32_t off =
                    (uint32_t)((wmB + mt * 16 + arow) * KSTRIDE + kb + acol8) * 2;
                ldsm4(af[mt], stg + STG_A + off);
            }
#pragma unroll
            for (int nt2 = 0; nt2 < 2; nt2++) {
                const uint32_t off =
                    (uint32_t)((wn + nt2 * 16 + brow) * KSTRIDE + kb + bcol8) * 2;
                ldsm4(bf[nt2], stg + STG_B + off);
            }
#pragma unroll
            for (int mt = 0; mt < 4; mt++)
#pragma unroll
                for (int nt = 0; nt < 4; nt++)
                    mma16816(acc[mt][nt], af[mt], &bf[nt >> 1][(nt & 1) * 2]);
        }
        if (kt + 2 < ntiles) issue(kt + 2, (kt + 2) % 3);
    }

    // -------- epilogue --------
    const int g = lane >> 2;
    const int t = lane & 3;
#pragma unroll
    for (int mt = 0; mt < 4; mt++)
#pragma unroll
        for (int nt = 0; nt < 4; nt++) {
            const int gcol = bn + wn + nt * 8 + t * 2;
            float b0 = 0.f, b1 = 0.f;
            if (bias) { b0 = __ldg(&bias[gcol]); b1 = __ldg(&bias[gcol + 1]); }
#pragma unroll
            for (int half_ = 0; half_ < 2; half_++) {
                const int grow = bm + wmB + mt * 16 + g + half_ * 8;
                float v0 = acc[mt][nt][half_ * 2 + 0] + b0;
                float v1 = acc[mt][nt][half_ * 2 + 1] + b1;
                if (flags & 1) { v0 = fmaxf(v0, 0.f); v1 = fmaxf(v1, 0.f); }
                const size_t o = (size_t)grow * N + gcol;
                if (flags & 4)
                    *(float2*)(Cf + o) = make_float2(v0, v1);
                if (flags & 2)
                    *(__half2*)(Ch + o) =
                        __halves2half2(__float2half_rn(v0), __float2half_rn(v1));
            }
        }
}

// ---------------------------------------------------------------------------
// Transpose + round weights to fp16: W[K,N] -> Wt[N,K]
// ---------------------------------------------------------------------------
__global__ void thalf_kernel(const float* __restrict__ W, __half* __restrict__ Th,
                             int Kd, int Nd)
{
    __shared__ float t[32][33];
    const int bx = blockIdx.x * 32;   // N
    const int by = blockIdx.y * 32;   // K
    const int x = threadIdx.x, y0 = threadIdx.y;
#pragma unroll
    for (int dy = 0; dy < 32; dy += 8)
        t[y0 + dy][x] = W[(size_t)(by + y0 + dy) * Nd + bx + x];
    __syncthreads();
#pragma unroll
    for (int dy = 0; dy < 32; dy += 8)
        Th[(size_t)(bx + y0 + dy) * Kd + by + x] = __float2half_rn(t[x][y0 + dy]);
}

// Elementwise fp32 -> fp16 (for x).
__global__ void tohalf_kernel(const float* __restrict__ in, __half* __restrict__ o,
                              int n4)
{
    int i = blockIdx.x * blockDim.x + threadIdx.x;
    if (i >= n4) return;
    float4 a = ((const float4*)in)[i];
    ((__half2*)o)[i * 2]     = __halves2half2(__float2half_rn(a.x), __float2half_rn(a.y));
    ((__half2*)o)[i * 2 + 1] = __halves2half2(__float2half_rn(a.z), __float2half_rn(a.w));
}

// ---------------------------------------------------------------------------
// Neighbor attention (K=8); reads fused qkv[M][3072] = q|k|v (fp32), writes fp16 ctx.
// ---------------------------------------------------------------------------
__global__ __launch_bounds__(256)
void attn_kernel(const float* __restrict__ qkv, const float* __restrict__ radj,
                 const int* __restrict__ inxs, __half* __restrict__ ctx)
{
    const int bt = blockIdx.x;
    const int b = bt >> 10;
    const int tid = threadIdx.x;
    const int wid = tid >> 5, lid = tid & 31;

    __shared__ float s_scores[KNEI];
    __shared__ int s_rows[KNEI];
    if (tid < KNEI) s_rows[tid] = b * TSEQ + inxs[(size_t)bt * KNEI + tid];
    __syncthreads();

    const float4* qv = (const float4*)(qkv + (size_t)bt * QKVLD);
    const float4* kv = (const float4*)(qkv + (size_t)s_rows[wid] * QKVLD + CDIM);
    float sum = 0.f;
#pragma unroll 4
    for (int e = lid; e < CDIM / 4; e += 32) {
        float4 a = qv[e], c = kv[e];
        sum += a.x * c.x + a.y * c.y + a.z * c.z + a.w * c.w;
    }
#pragma unroll
    for (int o = 16; o > 0; o >>= 1) sum += __shfl_xor_sync(0xffffffffu, sum, o);
    if (lid == 0)
        s_scores[wid] = sum * 0.03125f + radj[(size_t)bt * KNEI + wid];
    __syncthreads();

    float w[KNEI];
    float mx = s_scores[0];
#pragma unroll
    for (int j = 1; j < KNEI; j++) mx = fmaxf(mx, s_scores[j]);
    float den = 0.f;
#pragma unroll
    for (int j = 0; j < KNEI; j++) { w[j] = expf(s_scores[j] - mx); den += w[j]; }
    const float inv = 1.f / den;

    float4 o4 = make_float4(0.f, 0.f, 0.f, 0.f);
#pragma unroll
    for (int j = 0; j < KNEI; j++) {
        const float4 v =
            ((const float4*)(qkv + (size_t)s_rows[j] * QKVLD + 2 * CDIM))[tid];
        const float wj = w[j] * inv;
        o4.x = fmaf(wj, v.x, o4.x); o4.y = fmaf(wj, v.y, o4.y);
        o4.z = fmaf(wj, v.z, o4.z); o4.w = fmaf(wj, v.w, o4.w);
    }
    const size_t base2 = (size_t)bt * (CDIM / 2) + tid * 2;
    ((__half2*)ctx)[base2] =
        __halves2half2(__float2half_rn(o4.x), __float2half_rn(o4.y));
    ((__half2*)ctx)[base2 + 1] =
        __halves2half2(__float2half_rn(o4.z), __float2half_rn(o4.w));
}

// ---------------------------------------------------------------------------
// Fused residual (+optional relu) LayerNorm; optional fp16 extra output.
// ---------------------------------------------------------------------------
__global__ __launch_bounds__(256)
void ln_kernel(const float* __restrict__ a, const float* __restrict__ hb,
               const float* __restrict__ g, const float* __restrict__ beta,
               float* __restrict__ out, __half* __restrict__ oh, int relu_h)
{
    __shared__ float sh1[8], sh2[8];
    const int bt = blockIdx.x;
    const int tid = threadIdx.x;
    const int wid = tid >> 5, lid = tid & 31;
    const size_t base = (size_t)bt * CDIM;

    float4 z = ((const float4*)(a + base))[tid];
    float4 hh = ((const float4*)(hb + base))[tid];
    if (relu_h) {
        hh.x = fmaxf(hh.x, 0.f); hh.y = fmaxf(hh.y, 0.f);
        hh.z = fmaxf(hh.z, 0.f); hh.w = fmaxf(hh.w, 0.f);
    }
    z.x += hh.x; z.y += hh.y; z.z += hh.z; z.w += hh.w;

    float s = z.x + z.y + z.z + z.w;
    float ss = z.x * z.x + z.y * z.y + z.z * z.z + z.w * z.w;
#pragma unroll
    for (int o = 16; o > 0; o >>= 1) {
        s += __shfl_xor_sync(0xffffffffu, s, o);
        ss += __shfl_xor_sync(0xffffffffu, ss, o);
    }
    if (lid == 0) { sh1[wid] = s; sh2[wid] = ss; }
    __syncthreads();
    float ts = 0.f, tss = 0.f;
#pragma unroll
    for (int j = 0; j < 8; j++) { ts += sh1[j]; tss += sh2[j]; }

    const float mean = ts * (1.f / CDIM);
    const float var = tss * (1.f / CDIM) - mean * mean;
    const float rstd = rsqrtf(var + 1e-5f);

    const float4 gg = ((const float4*)g)[tid];
    const float4 bb = ((const float4*)beta)[tid];
    float4 o4;
    o4.x = (z.x - mean) * rstd * gg.x + bb.x;
    o4.y = (z.y - mean) * rstd * gg.y + bb.y;
    o4.z = (z.z - mean) * rstd * gg.z + bb.z;
    o4.w = (z.w - mean) * rstd * gg.w + bb.w;
    ((float4*)(out + base))[tid] = o4;
    if (oh) {
        const size_t b2 = (size_t)bt * (CDIM / 2) + tid * 2;
        ((__half2*)oh)[b2] =
            __halves2half2(__float2half_rn(o4.x), __float2half_rn(o4.y));
        ((__half2*)oh)[b2 + 1] =
            __halves2half2(__float2half_rn(o4.z), __float2half_rn(o4.w));
    }
}

// ---------------------------------------------------------------------------
// Launch
// ---------------------------------------------------------------------------
extern "C" void kernel_launch(void* const* d_in, const int* in_sizes, int n_in,
                              void* d_out, int out_size)
{
    const float* x    = (const float*)d_in[0];
    const float* radj = (const float*)d_in[1];
    const int*   inxs = (const int*)  d_in[2];
    const float* Wq   = (const float*)d_in[3];
    const float* Wk   = (const float*)d_in[4];
    const float* Wv   = (const float*)d_in[5];
    const float* Wo   = (const float*)d_in[6];
    const float* ln1g = (const float*)d_in[7];
    const float* ln1b = (const float*)d_in[8];
    const float* W1   = (const float*)d_in[9];
    const float* b1   = (const float*)d_in[10];
    const float* W2   = (const float*)d_in[11];
    const float* b2   = (const float*)d_in[12];
    const float* ln2g = (const float*)d_in[13];
    const float* ln2b = (const float*)d_in[14];
    float* out = (float*)d_out;

    float *qkv, *h32, *y, *f;
    __half *ctx, *h1, *yh, *xh, *hid, *wqkvh, *woh, *w1h, *w2h;
    cudaGetSymbolAddress((void**)&qkv, g_qkv);
    cudaGetSymbolAddress((void**)&ctx, g_ctx);
    cudaGetSymbolAddress((void**)&h1, g_h1);
    cudaGetSymbolAddress((void**)&h32, g_h32);
    cudaGetSymbolAddress((void**)&y, g_y);
    cudaGetSymbolAddress((void**)&yh, g_yh);
    cudaGetSymbolAddress((void**)&f, g_f);
    cudaGetSymbolAddress((void**)&xh, g_xh);
    cudaGetSymbolAddress((void**)&hid, g_hid);
    cudaGetSymbolAddress((void**)&wqkvh, g_wqkvh);
    cudaGetSymbolAddress((void**)&woh, g_woh);
    cudaGetSymbolAddress((void**)&w1h, g_w1h);
    cudaGetSymbolAddress((void**)&w2h, g_w2h);

    cudaFuncSetAttribute(mm_fp16_kernel,
                         cudaFuncAttributeMaxDynamicSharedMemorySize, MM_SMEM);

    const dim3 b256(256);
    const dim3 tblk(32, 8);

    // Weight transpose (fp16).  QKV stacked: rows 0-1023 Wq, 1024-2047 Wk, 2048-3071 Wv.
    thalf_kernel<<<dim3(CDIM / 32, CDIM / 32), tblk>>>(Wq, wqkvh, CDIM, CDIM);
    thalf_kernel<<<dim3(CDIM / 32, CDIM / 32), tblk>>>(Wk, wqkvh + (size_t)CDIM * CDIM, CDIM, CDIM);
    thalf_kernel<<<dim3(CDIM / 32, CDIM / 32), tblk>>>(Wv, wqkvh + (size_t)2 * CDIM * CDIM, CDIM, CDIM);
    thalf_kernel<<<dim3(CDIM / 32, CDIM / 32), tblk>>>(Wo, woh, CDIM, CDIM);
    thalf_kernel<<<dim3(HDIM / 32, CDIM / 32), tblk>>>(W1, w1h, CDIM, HDIM);
    thalf_kernel<<<dim3(CDIM / 32, HDIM / 32), tblk>>>(W2, w2h, HDIM, CDIM);
    tohalf_kernel<<<(MDIM * CDIM / 4 + 255) / 256, b256>>>(x, xh, MDIM * CDIM / 4);

    const dim3 gQKV(QKVLD / 128, MDIM / 128);  // (24, 128)
    const dim3 gCC(CDIM / 128, MDIM / 128);    // (8, 128)
    const dim3 gCH(HDIM / 128, MDIM / 128);    // (12, 128)

    const __half* a16 = xh;
    for (int hop = 0; hop < 2; hop++) {
        // fused q|k|v = A @ Wqkv^T  (fp32 out for attention)
        mm_fp16_kernel<<<gQKV, 256, MM_SMEM>>>(a16, wqkvh, qkv, nullptr,
                                               nullptr, QKVLD, CDIM, 4);
        attn_kernel<<<MDIM, b256>>>(qkv, radj, inxs, ctx);
        if (hop == 0) {
            mm_fp16_kernel<<<gCC, 256, MM_SMEM>>>(ctx, woh, nullptr, h1,
                                                  nullptr, CDIM, CDIM, 2);
            a16 = h1;
        } else {
            mm_fp16_kernel<<<gCC, 256, MM_SMEM>>>(ctx, woh, h32, nullptr,
                                                  nullptr, CDIM, CDIM, 4);
        }
    }

    // y = LN(x + relu(h));  + fp16 copy for FFN input
    ln_kernel<<<MDIM, b256>>>(x, h32, ln1g, ln1b, y, yh, 1);
    // hid = relu(y @ W1 + b1)  -> fp16
    mm_fp16_kernel<<<gCH, 256, MM_SMEM>>>(yh, w1h, nullptr, hid, b1, HDIM, CDIM, 1 | 2);
    // f = hid @ W2 + b2  -> fp32
    mm_fp16_kernel<<<gCC, 256, MM_SMEM>>>(hid, w2h, f, nullptr, b2, CDIM, HDIM, 4);
    // out = LN(y + f)
    ln_kernel<<<MDIM, b256>>>(y, f, ln2g, ln2b, out, nullptr, 0);
}

// round 7
// speedup vs baseline: 2.3870x; 1.0209x over previous
#include <cuda_runtime.h>
#include <cuda_fp16.h>
#include <cstdint>
#include <math.h>

// ============================================================================
// ReasonNet via ldmatrix + mma.sync (HMMA), pure fp16 GEMMs (fp32 accum).
// Round 7: fp16 end-to-end attention path — QKV GEMM writes fp16, attention
// gathers fp16 K/V (half the gather traffic), fp32 math inside.
// B=16, T=1024, C=1024, K=8, H=1536.  M = B*T = 16384.
// ============================================================================

#define MDIM 16384
#define CDIM 1024
#define HDIM 1536
#define KNEI 8
#define TSEQ 1024
#define QKVLD 3072

#define BK 32
#define KSTRIDE 40                  // halfs per smem row (80B: aligned + LDSM conflict-free)
#define ROWB 80
#define STG_A 0
#define STG_B 10240                 // 128*80
#define STG_BYTES 20480
#define MM_SMEM (3 * STG_BYTES)     // 61440 bytes

// ---------------------------------------------------------------------------
// Scratch (static device globals; runtime allocation forbidden).
// ---------------------------------------------------------------------------
__device__ __half g_qkv [(size_t)MDIM * QKVLD];   // fused q|k|v per hop (fp16)
__device__ __half g_ctx [(size_t)MDIM * CDIM];
__device__ __half g_h1  [(size_t)MDIM * CDIM];
__device__ float  g_h32 [(size_t)MDIM * CDIM];
__device__ float  g_y   [(size_t)MDIM * CDIM];
__device__ __half g_yh  [(size_t)MDIM * CDIM];
__device__ float  g_f   [(size_t)MDIM * CDIM];
__device__ __half g_xh  [(size_t)MDIM * CDIM];
__device__ __half g_hid [(size_t)MDIM * HDIM];
// Transposed fp16 weights: Wt[N][K].  QKV stacked (3072 rows).
__device__ __half g_wqkvh[(size_t)QKVLD * CDIM];
__device__ __half g_woh[(size_t)CDIM * CDIM];
__device__ __half g_w1h[(size_t)HDIM * CDIM];
__device__ __half g_w2h[(size_t)CDIM * HDIM];

// ---------------------------------------------------------------------------
// PTX helpers (sm_80-portable only)
// ---------------------------------------------------------------------------
__device__ __forceinline__ uint32_t smem_u32(const void* p) {
    uint32_t a;
    asm("{ .reg .u64 t; cvta.to.shared.u64 t, %1; cvt.u32.u64 %0, t; }"
        : "=r"(a) : "l"(p));
    return a;
}
__device__ __forceinline__ void cp16(uint32_t s, const void* g) {
    asm volatile("cp.async.cg.shared.global [%0], [%1], 16;" :: "r"(s), "l"(g) : "memory");
}
__device__ __forceinline__ void ldsm4(uint32_t* r, uint32_t addr) {
    asm volatile("ldmatrix.sync.aligned.m8n8.x4.shared.b16 {%0,%1,%2,%3}, [%4];"
                 : "=r"(r[0]), "=r"(r[1]), "=r"(r[2]), "=r"(r[3]) : "r"(addr));
}
__device__ __forceinline__ void mma16816(float* c, const uint32_t* a, const uint32_t* b) {
    asm volatile(
        "mma.sync.aligned.m16n8k16.row.col.f32.f16.f16.f32 "
        "{%0,%1,%2,%3}, {%4,%5,%6,%7}, {%8,%9}, {%0,%1,%2,%3};"
        : "+f"(c[0]), "+f"(c[1]), "+f"(c[2]), "+f"(c[3])
        : "r"(a[0]), "r"(a[1]), "r"(a[2]), "r"(a[3]), "r"(b[0]), "r"(b[1]));
}
// dot of 8 fp16 pairs (as uint4) accumulated in fp32
__device__ __forceinline__ float dot8(uint4 a, uint4 c) {
    const __half2* pa = (const __half2*)&a;
    const __half2* pc = (const __half2*)&c;
    float s = 0.f;
#pragma unroll
    for (int i = 0; i < 4; i++) {
        float2 fa = __half22float2(pa[i]);
        float2 fc = __half22float2(pc[i]);
        s += fa.x * fc.x + fa.y * fc.y;
    }
    return s;
}

// ---------------------------------------------------------------------------
// fp16 GEMM: C[M,N] = A[M,K] @ B[N,K]^T  (fp32 accumulate)
// flags: bit0 relu, bit1 write fp16 (Ch), bit2 write fp32 (Cf).
// 256 threads, 128x128 tile, BK=32, 3-stage cp.async pipeline.
// ---------------------------------------------------------------------------
__global__ __launch_bounds__(256, 2)
void mm_fp16_kernel(const __half* __restrict__ A, const __half* __restrict__ B,
                    float* __restrict__ Cf, __half* __restrict__ Ch,
                    const float* __restrict__ bias, int N, int K, int flags)
{
    extern __shared__ char smem[];
    const uint32_t sb = smem_u32(smem);
    const int tid  = threadIdx.x;
    const int wid  = tid >> 5;
    const int lane = tid & 31;
    const int bm   = blockIdx.y * 128;
    const int bn   = blockIdx.x * 128;
    const int wmB  = (wid >> 2) * 64;
    const int wn   = (wid & 3) * 32;
    const int ntiles = K / BK;

    // -------- producer addressing --------
    const int row = tid & 127;
    const int sg0 = tid >> 7;           // 0/1; covers segs sg0, sg0+2
    const __half* gA = A + (size_t)(bm + row) * K;
    const __half* gB = B + (size_t)(bn + row) * K;
    const uint32_t doff = (uint32_t)row * ROWB;

    auto issue = [&](int kt, int s) {
        const uint32_t st = sb + (uint32_t)s * STG_BYTES;
        const size_t kof = (size_t)kt * BK;
#pragma unroll
        for (int qq = 0; qq < 2; qq++) {
            const int seg = sg0 + qq * 2;
            const uint32_t d = doff + seg * 16;
            const size_t g = kof + seg * 8;
            cp16(st + STG_A + d, gA + g);
            cp16(st + STG_B + d, gB + g);
        }
        asm volatile("cp.async.commit_group;" ::: "memory");
    };

    float acc[4][4][4];
#pragma unroll
    for (int i = 0; i < 4; i++)
#pragma unroll
        for (int j = 0; j < 4; j++)
#pragma unroll
            for (int l = 0; l < 4; l++) acc[i][j][l] = 0.f;

    issue(0, 0);
    issue(1, 1);

    // ldmatrix lane addressing
    const int arow  = lane & 15;
    const int acol8 = (lane >> 4) * 8;
    const int brow  = (lane & 7) + ((lane >> 4) << 3);
    const int bcol8 = ((lane >> 3) & 1) * 8;

    for (int kt = 0; kt < ntiles; kt++) {
        if (kt == ntiles - 1)
            asm volatile("cp.async.wait_group 0;" ::: "memory");
        else
            asm volatile("cp.async.wait_group 1;" ::: "memory");
        __syncthreads();

        const uint32_t stg = sb + (uint32_t)(kt % 3) * STG_BYTES;
#pragma unroll
        for (int ks = 0; ks < 2; ks++) {
            const int kb = ks * 16;
            uint32_t af[4][4], bf[2][4];
#pragma unroll
            for (int mt = 0; mt < 4; mt++) {
                const uint32_t off =
                    (uint32_t)((wmB + mt * 16 + arow) * KSTRIDE + kb + acol8) * 2;
                ldsm4(af[mt], stg + STG_A + off);
            }
#pragma unroll
            for (int nt2 = 0; nt2 < 2; nt2++) {
                const uint32_t off =
                    (uint32_t)((wn + nt2 * 16 + brow) * KSTRIDE + kb + bcol8) * 2;
                ldsm4(bf[nt2], stg + STG_B + off);
            }
#pragma unroll
            for (int mt = 0; mt < 4; mt++)
#pragma unroll
                for (int nt = 0; nt < 4; nt++)
                    mma16816(acc[mt][nt], af[mt], &bf[nt >> 1][(nt & 1) * 2]);
        }
        if (kt + 2 < ntiles) issue(kt + 2, (kt + 2) % 3);
    }

    // -------- epilogue --------
    const int g = lane >> 2;
    const int t = lane & 3;
#pragma unroll
    for (int mt = 0; mt < 4; mt++)
#pragma unroll
        for (int nt = 0; nt < 4; nt++) {
            const int gcol = bn + wn + nt * 8 + t * 2;
            float b0 = 0.f, b1 = 0.f;
            if (bias) { b0 = __ldg(&bias[gcol]); b1 = __ldg(&bias[gcol + 1]); }
#pragma unroll
            for (int half_ = 0; half_ < 2; half_++) {
                const int grow = bm + wmB + mt * 16 + g + half_ * 8;
                float v0 = acc[mt][nt][half_ * 2 + 0] + b0;
                float v1 = acc[mt][nt][half_ * 2 + 1] + b1;
                if (flags & 1) { v0 = fmaxf(v0, 0.f); v1 = fmaxf(v1, 0.f); }
                const size_t o = (size_t)grow * N + gcol;
                if (flags & 4)
                    *(float2*)(Cf + o) = make_float2(v0, v1);
                if (flags & 2)
                    *(__half2*)(Ch + o) =
                        __halves2half2(__float2half_rn(v0), __float2half_rn(v1));
            }
        }
}

// ---------------------------------------------------------------------------
// Transpose + round weights to fp16: W[K,N] -> Wt[N,K]
// ---------------------------------------------------------------------------
__global__ void thalf_kernel(const float* __restrict__ W, __half* __restrict__ Th,
                             int Kd, int Nd)
{
    __shared__ float t[32][33];
    const int bx = blockIdx.x * 32;   // N
    const int by = blockIdx.y * 32;   // K
    const int x = threadIdx.x, y0 = threadIdx.y;
#pragma unroll
    for (int dy = 0; dy < 32; dy += 8)
        t[y0 + dy][x] = W[(size_t)(by + y0 + dy) * Nd + bx + x];
    __syncthreads();
#pragma unroll
    for (int dy = 0; dy < 32; dy += 8)
        Th[(size_t)(bx + y0 + dy) * Kd + by + x] = __float2half_rn(t[x][y0 + dy]);
}

// Elementwise fp32 -> fp16 (for x).
__global__ void tohalf_kernel(const float* __restrict__ in, __half* __restrict__ o,
                              int n4)
{
    int i = blockIdx.x * blockDim.x + threadIdx.x;
    if (i >= n4) return;
    float4 a = ((const float4*)in)[i];
    ((__half2*)o)[i * 2]     = __halves2half2(__float2half_rn(a.x), __float2half_rn(a.y));
    ((__half2*)o)[i * 2 + 1] = __halves2half2(__float2half_rn(a.z), __float2half_rn(a.w));
}

// ---------------------------------------------------------------------------
// Neighbor attention (K=8); fp16 qkv[M][3072] = q|k|v, fp32 math, fp16 ctx out.
// ---------------------------------------------------------------------------
__global__ __launch_bounds__(256)
void attn_kernel(const __half* __restrict__ qkv, const float* __restrict__ radj,
                 const int* __restrict__ inxs, __half* __restrict__ ctx)
{
    const int bt = blockIdx.x;
    const int b = bt >> 10;
    const int tid = threadIdx.x;
    const int wid = tid >> 5, lid = tid & 31;

    __shared__ float s_scores[KNEI];
    __shared__ int s_rows[KNEI];
    if (tid < KNEI) s_rows[tid] = b * TSEQ + inxs[(size_t)bt * KNEI + tid];
    __syncthreads();

    // scores: warp wid handles neighbor wid.  128 uint4 (8 halfs each) per row.
    const uint4* qv = (const uint4*)(qkv + (size_t)bt * QKVLD);
    const uint4* kv = (const uint4*)(qkv + (size_t)s_rows[wid] * QKVLD + CDIM);
    float sum = 0.f;
#pragma unroll
    for (int e = lid; e < CDIM / 8; e += 32)
        sum += dot8(qv[e], kv[e]);
#pragma unroll
    for (int o = 16; o > 0; o >>= 1) sum += __shfl_xor_sync(0xffffffffu, sum, o);
    if (lid == 0)
        s_scores[wid] = sum * 0.03125f + radj[(size_t)bt * KNEI + wid];
    __syncthreads();

    float w[KNEI];
    float mx = s_scores[0];
#pragma unroll
    for (int j = 1; j < KNEI; j++) mx = fmaxf(mx, s_scores[j]);
    float den = 0.f;
#pragma unroll
    for (int j = 0; j < KNEI; j++) { w[j] = expf(s_scores[j] - mx); den += w[j]; }
    const float inv = 1.f / den;

    // weighted V sum: thread tid owns 4 consecutive halfs (one uint2).
    float a0 = 0.f, a1 = 0.f, a2 = 0.f, a3 = 0.f;
#pragma unroll
    for (int j = 0; j < KNEI; j++) {
        const uint2 vv =
            ((const uint2*)(qkv + (size_t)s_rows[j] * QKVLD + 2 * CDIM))[tid];
        const __half2* pv = (const __half2*)&vv;
        const float2 f0 = __half22float2(pv[0]);
        const float2 f1 = __half22float2(pv[1]);
        const float wj = w[j] * inv;
        a0 = fmaf(wj, f0.x, a0); a1 = fmaf(wj, f0.y, a1);
        a2 = fmaf(wj, f1.x, a2); a3 = fmaf(wj, f1.y, a3);
    }
    uint2 ov;
    ((__half2*)&ov)[0] = __halves2half2(__float2half_rn(a0), __float2half_rn(a1));
    ((__half2*)&ov)[1] = __halves2half2(__float2half_rn(a2), __float2half_rn(a3));
    ((uint2*)(ctx + (size_t)bt * CDIM))[tid] = ov;
}

// ---------------------------------------------------------------------------
// Fused residual (+optional relu) LayerNorm; optional fp16 extra output.
// ---------------------------------------------------------------------------
__global__ __launch_bounds__(256)
void ln_kernel(const float* __restrict__ a, const float* __restrict__ hb,
               const float* __restrict__ g, const float* __restrict__ beta,
               float* __restrict__ out, __half* __restrict__ oh, int relu_h)
{
    __shared__ float sh1[8], sh2[8];
    const int bt = blockIdx.x;
    const int tid = threadIdx.x;
    const int wid = tid >> 5, lid = tid & 31;
    const size_t base = (size_t)bt * CDIM;

    float4 z = ((const float4*)(a + base))[tid];
    float4 hh = ((const float4*)(hb + base))[tid];
    if (relu_h) {
        hh.x = fmaxf(hh.x, 0.f); hh.y = fmaxf(hh.y, 0.f);
        hh.z = fmaxf(hh.z, 0.f); hh.w = fmaxf(hh.w, 0.f);
    }
    z.x += hh.x; z.y += hh.y; z.z += hh.z; z.w += hh.w;

    float s = z.x + z.y + z.z + z.w;
    float ss = z.x * z.x + z.y * z.y + z.z * z.z + z.w * z.w;
#pragma unroll
    for (int o = 16; o > 0; o >>= 1) {
        s += __shfl_xor_sync(0xffffffffu, s, o);
        ss += __shfl_xor_sync(0xffffffffu, ss, o);
    }
    if (lid == 0) { sh1[wid] = s; sh2[wid] = ss; }
    __syncthreads();
    float ts = 0.f, tss = 0.f;
#pragma unroll
    for (int j = 0; j < 8; j++) { ts += sh1[j]; tss += sh2[j]; }

    const float mean = ts * (1.f / CDIM);
    const float var = tss * (1.f / CDIM) - mean * mean;
    const float rstd = rsqrtf(var + 1e-5f);

    const float4 gg = ((const float4*)g)[tid];
    const float4 bb = ((const float4*)beta)[tid];
    float4 o4;
    o4.x = (z.x - mean) * rstd * gg.x + bb.x;
    o4.y = (z.y - mean) * rstd * gg.y + bb.y;
    o4.z = (z.z - mean) * rstd * gg.z + bb.z;
    o4.w = (z.w - mean) * rstd * gg.w + bb.w;
    ((float4*)(out + base))[tid] = o4;
    if (oh) {
        const size_t b2 = (size_t)bt * (CDIM / 2) + tid * 2;
        ((__half2*)oh)[b2] =
            __halves2half2(__float2half_rn(o4.x), __float2half_rn(o4.y));
        ((__half2*)oh)[b2 + 1] =
            __halves2half2(__float2half_rn(o4.z), __float2half_rn(o4.w));
    }
}

// ---------------------------------------------------------------------------
// Launch
// ---------------------------------------------------------------------------
extern "C" void kernel_launch(void* const* d_in, const int* in_sizes, int n_in,
                              void* d_out, int out_size)
{
    const float* x    = (const float*)d_in[0];
    const float* radj = (const float*)d_in[1];
    const int*   inxs = (const int*)  d_in[2];
    const float* Wq   = (const float*)d_in[3];
    const float* Wk   = (const float*)d_in[4];
    const float* Wv   = (const float*)d_in[5];
    const float* Wo   = (const float*)d_in[6];
    const float* ln1g = (const float*)d_in[7];
    const float* ln1b = (const float*)d_in[8];
    const float* W1   = (const float*)d_in[9];
    const float* b1   = (const float*)d_in[10];
    const float* W2   = (const float*)d_in[11];
    const float* b2   = (const float*)d_in[12];
    const float* ln2g = (const float*)d_in[13];
    const float* ln2b = (const float*)d_in[14];
    float* out = (float*)d_out;

    float *h32, *y, *f;
    __half *qkv, *ctx, *h1, *yh, *xh, *hid, *wqkvh, *woh, *w1h, *w2h;
    cudaGetSymbolAddress((void**)&qkv, g_qkv);
    cudaGetSymbolAddress((void**)&ctx, g_ctx);
    cudaGetSymbolAddress((void**)&h1, g_h1);
    cudaGetSymbolAddress((void**)&h32, g_h32);
    cudaGetSymbolAddress((void**)&y, g_y);
    cudaGetSymbolAddress((void**)&yh, g_yh);
    cudaGetSymbolAddress((void**)&f, g_f);
    cudaGetSymbolAddress((void**)&xh, g_xh);
    cudaGetSymbolAddress((void**)&hid, g_hid);
    cudaGetSymbolAddress((void**)&wqkvh, g_wqkvh);
    cudaGetSymbolAddress((void**)&woh, g_woh);
    cudaGetSymbolAddress((void**)&w1h, g_w1h);
    cudaGetSymbolAddress((void**)&w2h, g_w2h);

    cudaFuncSetAttribute(mm_fp16_kernel,
                         cudaFuncAttributeMaxDynamicSharedMemorySize, MM_SMEM);

    const dim3 b256(256);
    const dim3 tblk(32, 8);

    // Weight transpose (fp16).  QKV stacked: rows 0-1023 Wq, 1024-2047 Wk, 2048-3071 Wv.
    thalf_kernel<<<dim3(CDIM / 32, CDIM / 32), tblk>>>(Wq, wqkvh, CDIM, CDIM);
    thalf_kernel<<<dim3(CDIM / 32, CDIM / 32), tblk>>>(Wk, wqkvh + (size_t)CDIM * CDIM, CDIM, CDIM);
    thalf_kernel<<<dim3(CDIM / 32, CDIM / 32), tblk>>>(Wv, wqkvh + (size_t)2 * CDIM * CDIM, CDIM, CDIM);
    thalf_kernel<<<dim3(CDIM / 32, CDIM / 32), tblk>>>(Wo, woh, CDIM, CDIM);
    thalf_kernel<<<dim3(HDIM / 32, CDIM / 32), tblk>>>(W1, w1h, CDIM, HDIM);
    thalf_kernel<<<dim3(CDIM / 32, HDIM / 32), tblk>>>(W2, w2h, HDIM, CDIM);
    tohalf_kernel<<<(MDIM * CDIM / 4 + 255) / 256, b256>>>(x, xh, MDIM * CDIM / 4);

    const dim3 gQKV(QKVLD / 128, MDIM / 128);  // (24, 128)
    const dim3 gCC(CDIM / 128, MDIM / 128);    // (8, 128)
    const dim3 gCH(HDIM / 128, MDIM / 128);    // (12, 128)

    const __half* a16 = xh;
    for (int hop = 0; hop < 2; hop++) {
        // fused q|k|v = A @ Wqkv^T  (fp16 out)
        mm_fp16_kernel<<<gQKV, 256, MM_SMEM>>>(a16, wqkvh, nullptr, qkv,
                                               nullptr, QKVLD, CDIM, 2);
        attn_kernel<<<MDIM, b256>>>(qkv, radj, inxs, ctx);
        if (hop == 0) {
            mm_fp16_kernel<<<gCC, 256, MM_SMEM>>>(ctx, woh, nullptr, h1,
                                                  nullptr, CDIM, CDIM, 2);
            a16 = h1;
        } else {
            mm_fp16_kernel<<<gCC, 256, MM_SMEM>>>(ctx, woh, h32, nullptr,
                                                  nullptr, CDIM, CDIM, 4);
        }
    }

    // y = LN(x + relu(h));  + fp16 copy for FFN input
    ln_kernel<<<MDIM, b256>>>(x, h32, ln1g, ln1b, y, yh, 1);
    // hid = relu(y @ W1 + b1)  -> fp16
    mm_fp16_kernel<<<gCH, 256, MM_SMEM>>>(yh, w1h, nullptr, hid, b1, HDIM, CDIM, 1 | 2);
    // f = hid @ W2 + b2  -> fp32
    mm_fp16_kernel<<<gCC, 256, MM_SMEM>>>(hid, w2h, f, nullptr, b2, CDIM, HDIM, 4);
    // out = LN(y + f)
    ln_kernel<<<MDIM, b256>>>(y, f, ln2g, ln2b, out, nullptr, 0);
}

// round 8
// speedup vs baseline: 2.4065x; 1.0081x over previous
#include <cuda_runtime.h>
#include <cuda_fp16.h>
#include <cstdint>
#include <math.h>

// ============================================================================
// ReasonNet via ldmatrix + mma.sync (HMMA), pure fp16 GEMMs (fp32 accum).
// Round 8: merged weight-prep launch (GEMM now at ncu capture index 5),
// 4-stage cp.async pipeline, all fp16 intermediates.
// B=16, T=1024, C=1024, K=8, H=1536.  M = B*T = 16384.
// ============================================================================

#define MDIM 16384
#define CDIM 1024
#define HDIM 1536
#define KNEI 8
#define TSEQ 1024
#define QKVLD 3072

#define BK 32
#define KSTRIDE 40                  // halfs per smem row (80B: aligned + LDSM conflict-free)
#define ROWB 80
#define STG_A 0
#define STG_B 10240                 // 128*80
#define STG_BYTES 20480
#define NSTG 4
#define MM_SMEM (NSTG * STG_BYTES)  // 81920 bytes (2 CTAs/SM: 163840 <= 227KB)

// ---------------------------------------------------------------------------
// Scratch (static device globals; runtime allocation forbidden).
// ---------------------------------------------------------------------------
__device__ __half g_qkv [(size_t)MDIM * QKVLD];   // fused q|k|v per hop (fp16)
__device__ __half g_ctx [(size_t)MDIM * CDIM];
__device__ __half g_h1  [(size_t)MDIM * CDIM];    // Wo output (both hops)
__device__ float  g_y   [(size_t)MDIM * CDIM];
__device__ __half g_yh  [(size_t)MDIM * CDIM];
__device__ __half g_f16 [(size_t)MDIM * CDIM];
__device__ __half g_xh  [(size_t)MDIM * CDIM];
__device__ __half g_hid [(size_t)MDIM * HDIM];
// Transposed fp16 weights: Wt[N][K].  QKV stacked (3072 rows).
__device__ __half g_wqkvh[(size_t)QKVLD * CDIM];
__device__ __half g_woh[(size_t)CDIM * CDIM];
__device__ __half g_w1h[(size_t)HDIM * CDIM];
__device__ __half g_w2h[(size_t)CDIM * HDIM];

// ---------------------------------------------------------------------------
// PTX helpers (sm_80-portable only)
// ---------------------------------------------------------------------------
__device__ __forceinline__ uint32_t smem_u32(const void* p) {
    uint32_t a;
    asm("{ .reg .u64 t; cvta.to.shared.u64 t, %1; cvt.u32.u64 %0, t; }"
        : "=r"(a) : "l"(p));
    return a;
}
__device__ __forceinline__ void cp16(uint32_t s, const void* g) {
    asm volatile("cp.async.cg.shared.global [%0], [%1], 16;" :: "r"(s), "l"(g) : "memory");
}
__device__ __forceinline__ void ldsm4(uint32_t* r, uint32_t addr) {
    asm volatile("ldmatrix.sync.aligned.m8n8.x4.shared.b16 {%0,%1,%2,%3}, [%4];"
                 : "=r"(r[0]), "=r"(r[1]), "=r"(r[2]), "=r"(r[3]) : "r"(addr));
}
__device__ __forceinline__ void mma16816(float* c, const uint32_t* a, const uint32_t* b) {
    asm volatile(
        "mma.sync.aligned.m16n8k16.row.col.f32.f16.f16.f32 "
        "{%0,%1,%2,%3}, {%4,%5,%6,%7}, {%8,%9}, {%0,%1,%2,%3};"
        : "+f"(c[0]), "+f"(c[1]), "+f"(c[2]), "+f"(c[3])
        : "r"(a[0]), "r"(a[1]), "r"(a[2]), "r"(a[3]), "r"(b[0]), "r"(b[1]));
}
// dot of 8 fp16 pairs (as uint4) accumulated in fp32
__device__ __forceinline__ float dot8(uint4 a, uint4 c) {
    const __half2* pa = (const __half2*)&a;
    const __half2* pc = (const __half2*)&c;
    float s = 0.f;
#pragma unroll
    for (int i = 0; i < 4; i++) {
        float2 fa = __half22float2(pa[i]);
        float2 fc = __half22float2(pc[i]);
        s += fa.x * fc.x + fa.y * fc.y;
    }
    return s;
}

// ---------------------------------------------------------------------------
// fp16 GEMM: C[M,N] = A[M,K] @ B[N,K]^T  (fp32 accumulate)
// flags: bit0 relu, bit1 write fp16 (Ch), bit2 write fp32 (Cf).
// 256 threads, 128x128 tile, BK=32, 4-stage cp.async pipeline.
// ---------------------------------------------------------------------------
__global__ __launch_bounds__(256, 2)
void mm_fp16_kernel(const __half* __restrict__ A, const __half* __restrict__ B,
                    float* __restrict__ Cf, __half* __restrict__ Ch,
                    const float* __restrict__ bias, int N, int K, int flags)
{
    extern __shared__ char smem[];
    const uint32_t sb = smem_u32(smem);
    const int tid  = threadIdx.x;
    const int wid  = tid >> 5;
    const int lane = tid & 31;
    const int bm   = blockIdx.y * 128;
    const int bn   = blockIdx.x * 128;
    const int wmB  = (wid >> 2) * 64;
    const int wn   = (wid & 3) * 32;
    const int ntiles = K / BK;

    // -------- producer addressing --------
    const int row = tid & 127;
    const int sg0 = tid >> 7;           // 0/1; covers segs sg0, sg0+2
    const __half* gA = A + (size_t)(bm + row) * K;
    const __half* gB = B + (size_t)(bn + row) * K;
    const uint32_t doff = (uint32_t)row * ROWB;

    auto issue = [&](int kt, int s) {
        const uint32_t st = sb + (uint32_t)s * STG_BYTES;
        const size_t kof = (size_t)kt * BK;
#pragma unroll
        for (int qq = 0; qq < 2; qq++) {
            const int seg = sg0 + qq * 2;
            const uint32_t d = doff + seg * 16;
            const size_t g = kof + seg * 8;
            cp16(st + STG_A + d, gA + g);
            cp16(st + STG_B + d, gB + g);
        }
        asm volatile("cp.async.commit_group;" ::: "memory");
    };

    float acc[4][4][4];
#pragma unroll
    for (int i = 0; i < 4; i++)
#pragma unroll
        for (int j = 0; j < 4; j++)
#pragma unroll
            for (int l = 0; l < 4; l++) acc[i][j][l] = 0.f;

    issue(0, 0);
    issue(1, 1);
    issue(2, 2);

    // ldmatrix lane addressing
    const int arow  = lane & 15;
    const int acol8 = (lane >> 4) * 8;
    const int brow  = (lane & 7) + ((lane >> 4) << 3);
    const int bcol8 = ((lane >> 3) & 1) * 8;

    for (int kt = 0; kt < ntiles; kt++) {
        // groups issued so far = min(kt+3, ntiles); ensure group kt complete.
        if (kt < ntiles - 2)
            asm volatile("cp.async.wait_group 2;" ::: "memory");
        else if (kt == ntiles - 2)
            asm volatile("cp.async.wait_group 1;" ::: "memory");
        else
            asm volatile("cp.async.wait_group 0;" ::: "memory");
        __syncthreads();

        const uint32_t stg = sb + (uint32_t)(kt % NSTG) * STG_BYTES;
#pragma unroll
        for (int ks = 0; ks < 2; ks++) {
            const int kb = ks * 16;
            uint32_t af[4][4], bf[2][4];
#pragma unroll
            for (int mt = 0; mt < 4; mt++) {
                const uint32_t off =
                    (uint32_t)((wmB + mt * 16 + arow) * KSTRIDE + kb + acol8) * 2;
                ldsm4(af[mt], stg + STG_A + off);
            }
#pragma unroll
            for (int nt2 = 0; nt2 < 2; nt2++) {
                const uint32_t off =
                    (uint32_t)((wn + nt2 * 16 + brow) * KSTRIDE + kb + bcol8) * 2;
                ldsm4(bf[nt2], stg + STG_B + off);
            }
#pragma unroll
            for (int mt = 0; mt < 4; mt++)
#pragma unroll
                for (int nt = 0; nt < 4; nt++)
                    mma16816(acc[mt][nt], af[mt], &bf[nt >> 1][(nt & 1) * 2]);
        }
        if (kt + 3 < ntiles) issue(kt + 3, (kt + 3) % NSTG);
    }

    // -------- epilogue --------
    const int g = lane >> 2;
    const int t = lane & 3;
#pragma unroll
    for (int mt = 0; mt < 4; mt++)
#pragma unroll
        for (int nt = 0; nt < 4; nt++) {
            const int gcol = bn + wn + nt * 8 + t * 2;
            float b0 = 0.f, b1 = 0.f;
            if (bias) { b0 = __ldg(&bias[gcol]); b1 = __ldg(&bias[gcol + 1]); }
#pragma unroll
            for (int half_ = 0; half_ < 2; half_++) {
                const int grow = bm + wmB + mt * 16 + g + half_ * 8;
                float v0 = acc[mt][nt][half_ * 2 + 0] + b0;
                float v1 = acc[mt][nt][half_ * 2 + 1] + b1;
                if (flags & 1) { v0 = fmaxf(v0, 0.f); v1 = fmaxf(v1, 0.f); }
                const size_t o = (size_t)grow * N + gcol;
                if (flags & 4)
                    *(float2*)(Cf + o) = make_float2(v0, v1);
                if (flags & 2)
                    *(__half2*)(Ch + o) =
                        __halves2half2(__float2half_rn(v0), __float2half_rn(v1));
            }
        }
}

// ---------------------------------------------------------------------------
// ALL weight transposes in ONE launch.  blockIdx.z selects the matrix.
// Transposes W[Kd,Nd] (row-major) -> Wt[Nd,Kd] fp16.
// ---------------------------------------------------------------------------
__global__ void thalf_all_kernel(const float* __restrict__ Wq, const float* __restrict__ Wk,
                                 const float* __restrict__ Wv, const float* __restrict__ Wo,
                                 const float* __restrict__ W1, const float* __restrict__ W2,
                                 __half* __restrict__ wqkv, __half* __restrict__ wo,
                                 __half* __restrict__ w1, __half* __restrict__ w2)
{
    const float* W;
    __half* T;
    int Kd, Nd;
    switch (blockIdx.z) {
        case 0: W = Wq; T = wqkv;                          Kd = CDIM; Nd = CDIM; break;
        case 1: W = Wk; T = wqkv + (size_t)CDIM * CDIM;    Kd = CDIM; Nd = CDIM; break;
        case 2: W = Wv; T = wqkv + (size_t)2 * CDIM * CDIM; Kd = CDIM; Nd = CDIM; break;
        case 3: W = Wo; T = wo;                            Kd = CDIM; Nd = CDIM; break;
        case 4: W = W1; T = w1;                            Kd = CDIM; Nd = HDIM; break;
        default: W = W2; T = w2;                           Kd = HDIM; Nd = CDIM; break;
    }
    const int bx = blockIdx.x * 32;   // N
    const int by = blockIdx.y * 32;   // K
    if (bx >= Nd || by >= Kd) return;

    __shared__ float t[32][33];
    const int x = threadIdx.x, y0 = threadIdx.y;
#pragma unroll
    for (int dy = 0; dy < 32; dy += 8)
        t[y0 + dy][x] = W[(size_t)(by + y0 + dy) * Nd + bx + x];
    __syncthreads();
#pragma unroll
    for (int dy = 0; dy < 32; dy += 8)
        T[(size_t)(bx + y0 + dy) * Kd + by + x] = __float2half_rn(t[x][y0 + dy]);
}

// Elementwise fp32 -> fp16 (for x).
__global__ void tohalf_kernel(const float* __restrict__ in, __half* __restrict__ o,
                              int n4)
{
    int i = blockIdx.x * blockDim.x + threadIdx.x;
    if (i >= n4) return;
    float4 a = ((const float4*)in)[i];
    ((__half2*)o)[i * 2]     = __halves2half2(__float2half_rn(a.x), __float2half_rn(a.y));
    ((__half2*)o)[i * 2 + 1] = __halves2half2(__float2half_rn(a.z), __float2half_rn(a.w));
}

// ---------------------------------------------------------------------------
// Neighbor attention (K=8); fp16 qkv[M][3072] = q|k|v, fp32 math, fp16 ctx out.
// ---------------------------------------------------------------------------
__global__ __launch_bounds__(256)
void attn_kernel(const __half* __restrict__ qkv, const float* __restrict__ radj,
                 const int* __restrict__ inxs, __half* __restrict__ ctx)
{
    const int bt = blockIdx.x;
    const int b = bt >> 10;
    const int tid = threadIdx.x;
    const int wid = tid >> 5, lid = tid & 31;

    __shared__ float s_scores[KNEI];
    __shared__ int s_rows[KNEI];
    if (tid < KNEI) s_rows[tid] = b * TSEQ + inxs[(size_t)bt * KNEI + tid];
    __syncthreads();

    const uint4* qv = (const uint4*)(qkv + (size_t)bt * QKVLD);
    const uint4* kv = (const uint4*)(qkv + (size_t)s_rows[wid] * QKVLD + CDIM);
    float sum = 0.f;
#pragma unroll
    for (int e = lid; e < CDIM / 8; e += 32)
        sum += dot8(qv[e], kv[e]);
#pragma unroll
    for (int o = 16; o > 0; o >>= 1) sum += __shfl_xor_sync(0xffffffffu, sum, o);
    if (lid == 0)
        s_scores[wid] = sum * 0.03125f + radj[(size_t)bt * KNEI + wid];
    __syncthreads();

    float w[KNEI];
    float mx = s_scores[0];
#pragma unroll
    for (int j = 1; j < KNEI; j++) mx = fmaxf(mx, s_scores[j]);
    float den = 0.f;
#pragma unroll
    for (int j = 0; j < KNEI; j++) { w[j] = expf(s_scores[j] - mx); den += w[j]; }
    const float inv = 1.f / den;

    float a0 = 0.f, a1 = 0.f, a2 = 0.f, a3 = 0.f;
#pragma unroll
    for (int j = 0; j < KNEI; j++) {
        const uint2 vv =
            ((const uint2*)(qkv + (size_t)s_rows[j] * QKVLD + 2 * CDIM))[tid];
        const __half2* pv = (const __half2*)&vv;
        const float2 f0 = __half22float2(pv[0]);
        const float2 f1 = __half22float2(pv[1]);
        const float wj = w[j] * inv;
        a0 = fmaf(wj, f0.x, a0); a1 = fmaf(wj, f0.y, a1);
        a2 = fmaf(wj, f1.x, a2); a3 = fmaf(wj, f1.y, a3);
    }
    uint2 ov;
    ((__half2*)&ov)[0] = __halves2half2(__float2half_rn(a0), __float2half_rn(a1));
    ((__half2*)&ov)[1] = __halves2half2(__float2half_rn(a2), __float2half_rn(a3));
    ((uint2*)(ctx + (size_t)bt * CDIM))[tid] = ov;
}

// ---------------------------------------------------------------------------
// Fused residual (+optional relu) LayerNorm.  Residual branch hb is fp16.
// Optional fp16 extra output oh.
// ---------------------------------------------------------------------------
__global__ __launch_bounds__(256)
void ln_kernel(const float* __restrict__ a, const __half* __restrict__ hb,
               const float* __restrict__ g, const float* __restrict__ beta,
               float* __restrict__ out, __half* __restrict__ oh, int relu_h)
{
    __shared__ float sh1[8], sh2[8];
    const int bt = blockIdx.x;
    const int tid = threadIdx.x;
    const int wid = tid >> 5, lid = tid & 31;
    const size_t base = (size_t)bt * CDIM;

    float4 z = ((const float4*)(a + base))[tid];
    const uint2 hv = ((const uint2*)(hb + base))[tid];
    const __half2* ph = (const __half2*)&hv;
    const float2 h01 = __half22float2(ph[0]);
    const float2 h23 = __half22float2(ph[1]);
    float hx = h01.x, hy = h01.y, hz = h23.x, hw = h23.y;
    if (relu_h) {
        hx = fmaxf(hx, 0.f); hy = fmaxf(hy, 0.f);
        hz = fmaxf(hz, 0.f); hw = fmaxf(hw, 0.f);
    }
    z.x += hx; z.y += hy; z.z += hz; z.w += hw;

    float s = z.x + z.y + z.z + z.w;
    float ss = z.x * z.x + z.y * z.y + z.z * z.z + z.w * z.w;
#pragma unroll
    for (int o = 16; o > 0; o >>= 1) {
        s += __shfl_xor_sync(0xffffffffu, s, o);
        ss += __shfl_xor_sync(0xffffffffu, ss, o);
    }
    if (lid == 0) { sh1[wid] = s; sh2[wid] = ss; }
    __syncthreads();
    float ts = 0.f, tss = 0.f;
#pragma unroll
    for (int j = 0; j < 8; j++) { ts += sh1[j]; tss += sh2[j]; }

    const float mean = ts * (1.f / CDIM);
    const float var = tss * (1.f / CDIM) - mean * mean;
    const float rstd = rsqrtf(var + 1e-5f);

    const float4 gg = ((const float4*)g)[tid];
    const float4 bb = ((const float4*)beta)[tid];
    float4 o4;
    o4.x = (z.x - mean) * rstd * gg.x + bb.x;
    o4.y = (z.y - mean) * rstd * gg.y + bb.y;
    o4.z = (z.z - mean) * rstd * gg.z + bb.z;
    o4.w = (z.w - mean) * rstd * gg.w + bb.w;
    ((float4*)(out + base))[tid] = o4;
    if (oh) {
        const size_t b2 = (size_t)bt * (CDIM / 2) + tid * 2;
        ((__half2*)oh)[b2] =
            __halves2half2(__float2half_rn(o4.x), __float2half_rn(o4.y));
        ((__half2*)oh)[b2 + 1] =
            __halves2half2(__float2half_rn(o4.z), __float2half_rn(o4.w));
    }
}

// ---------------------------------------------------------------------------
// Launch
// ---------------------------------------------------------------------------
extern "C" void kernel_launch(void* const* d_in, const int* in_sizes, int n_in,
                              void* d_out, int out_size)
{
    const float* x    = (const float*)d_in[0];
    const float* radj = (const float*)d_in[1];
    const int*   inxs = (const int*)  d_in[2];
    const float* Wq   = (const float*)d_in[3];
    const float* Wk   = (const float*)d_in[4];
    const float* Wv   = (const float*)d_in[5];
    const float* Wo   = (const float*)d_in[6];
    const float* ln1g = (const float*)d_in[7];
    const float* ln1b = (const float*)d_in[8];
    const float* W1   = (const float*)d_in[9];
    const float* b1   = (const float*)d_in[10];
    const float* W2   = (const float*)d_in[11];
    const float* b2   = (const float*)d_in[12];
    const float* ln2g = (const float*)d_in[13];
    const float* ln2b = (const float*)d_in[14];
    float* out = (float*)d_out;

    float *y;
    __half *qkv, *ctx, *h1, *yh, *f16, *xh, *hid, *wqkvh, *woh, *w1h, *w2h;
    cudaGetSymbolAddress((void**)&qkv, g_qkv);
    cudaGetSymbolAddress((void**)&ctx, g_ctx);
    cudaGetSymbolAddress((void**)&h1, g_h1);
    cudaGetSymbolAddress((void**)&y, g_y);
    cudaGetSymbolAddress((void**)&yh, g_yh);
    cudaGetSymbolAddress((void**)&f16, g_f16);
    cudaGetSymbolAddress((void**)&xh, g_xh);
    cudaGetSymbolAddress((void**)&hid, g_hid);
    cudaGetSymbolAddress((void**)&wqkvh, g_wqkvh);
    cudaGetSymbolAddress((void**)&woh, g_woh);
    cudaGetSymbolAddress((void**)&w1h, g_w1h);
    cudaGetSymbolAddress((void**)&w2h, g_w2h);

    cudaFuncSetAttribute(mm_fp16_kernel,
                         cudaFuncAttributeMaxDynamicSharedMemorySize, MM_SMEM);

    const dim3 b256(256);

    // Launch 0: all weight transposes (z = 6 segments, bounds-checked).
    thalf_all_kernel<<<dim3(HDIM / 32, HDIM / 32, 6), dim3(32, 8)>>>(
        Wq, Wk, Wv, Wo, W1, W2, wqkvh, woh, w1h, w2h);
    // Launch 1: x -> fp16
    tohalf_kernel<<<(MDIM * CDIM / 4 + 255) / 256, b256>>>(x, xh, MDIM * CDIM / 4);

    const dim3 gQKV(QKVLD / 128, MDIM / 128);  // (24, 128)
    const dim3 gCC(CDIM / 128, MDIM / 128);    // (8, 128)
    const dim3 gCH(HDIM / 128, MDIM / 128);    // (12, 128)

    const __half* a16 = xh;
    for (int hop = 0; hop < 2; hop++) {
        // launches 2 & 5: QKV GEMM (launch 5 is the ncu-captured one)
        mm_fp16_kernel<<<gQKV, 256, MM_SMEM>>>(a16, wqkvh, nullptr, qkv,
                                               nullptr, QKVLD, CDIM, 2);
        attn_kernel<<<MDIM, b256>>>(qkv, radj, inxs, ctx);
        mm_fp16_kernel<<<gCC, 256, MM_SMEM>>>(ctx, woh, nullptr, h1,
                                              nullptr, CDIM, CDIM, 2);
        a16 = h1;
    }

    // y = LN(x + relu(h));  + fp16 copy for FFN input
    ln_kernel<<<MDIM, b256>>>(x, h1, ln1g, ln1b, y, yh, 1);
    // hid = relu(y @ W1 + b1)  -> fp16
    mm_fp16_kernel<<<gCH, 256, MM_SMEM>>>(yh, w1h, nullptr, hid, b1, HDIM, CDIM, 1 | 2);
    // f = hid @ W2 + b2  -> fp16
    mm_fp16_kernel<<<gCC, 256, MM_SMEM>>>(hid, w2h, nullptr, f16, b2, CDIM, HDIM, 2);
    // out = LN(y + f)
    ln_kernel<<<MDIM, b256>>>(y, f16, ln2g, ln2b, out, nullptr, 0);
}

// round 9
// speedup vs baseline: 2.5659x; 1.0662x over previous
#include <cuda_runtime.h>
#include <cuda_fp16.h>
#include <cstdint>
#include <math.h>

// ============================================================================
// ReasonNet via ldmatrix + mma.sync (HMMA), pure fp16 GEMMs (fp32 accum).
// Round 9: 128x256 CTA tile, 64x64 warp tile (LDSM per MMA cut 1.5x),
// 4-stage cp.async.  Tests the shared-pipe-bound hypothesis.
// B=16, T=1024, C=1024, K=8, H=1536.  M = B*T = 16384.
// ============================================================================

#define MDIM 16384
#define CDIM 1024
#define HDIM 1536
#define KNEI 8
#define TSEQ 1024
#define QKVLD 3072

#define BK 32
#define KSTRIDE 40                  // halfs per smem row (80B: aligned + LDSM conflict-free)
#define ROWB 80
#define BM 128
#define BN 256
#define STG_A 0
#define STG_B 10240                 // 128*80
#define STG_BYTES 30720             // + 256*80
#define NSTG 4
#define MM_SMEM (NSTG * STG_BYTES)  // 122880 bytes (1 CTA/SM)

// ---------------------------------------------------------------------------
// Scratch (static device globals; runtime allocation forbidden).
// ---------------------------------------------------------------------------
__device__ __half g_qkv [(size_t)MDIM * QKVLD];   // fused q|k|v per hop (fp16)
__device__ __half g_ctx [(size_t)MDIM * CDIM];
__device__ __half g_h1  [(size_t)MDIM * CDIM];    // Wo output (both hops)
__device__ float  g_y   [(size_t)MDIM * CDIM];
__device__ __half g_yh  [(size_t)MDIM * CDIM];
__device__ __half g_f16 [(size_t)MDIM * CDIM];
__device__ __half g_xh  [(size_t)MDIM * CDIM];
__device__ __half g_hid [(size_t)MDIM * HDIM];
// Transposed fp16 weights: Wt[N][K].  QKV stacked (3072 rows).
__device__ __half g_wqkvh[(size_t)QKVLD * CDIM];
__device__ __half g_woh[(size_t)CDIM * CDIM];
__device__ __half g_w1h[(size_t)HDIM * CDIM];
__device__ __half g_w2h[(size_t)CDIM * HDIM];

// ---------------------------------------------------------------------------
// PTX helpers (sm_80-portable only)
// ---------------------------------------------------------------------------
__device__ __forceinline__ uint32_t smem_u32(const void* p) {
    uint32_t a;
    asm("{ .reg .u64 t; cvta.to.shared.u64 t, %1; cvt.u32.u64 %0, t; }"
        : "=r"(a) : "l"(p));
    return a;
}
__device__ __forceinline__ void cp16(uint32_t s, const void* g) {
    asm volatile("cp.async.cg.shared.global [%0], [%1], 16;" :: "r"(s), "l"(g) : "memory");
}
__device__ __forceinline__ void ldsm4(uint32_t* r, uint32_t addr) {
    asm volatile("ldmatrix.sync.aligned.m8n8.x4.shared.b16 {%0,%1,%2,%3}, [%4];"
                 : "=r"(r[0]), "=r"(r[1]), "=r"(r[2]), "=r"(r[3]) : "r"(addr));
}
__device__ __forceinline__ void mma16816(float* c, const uint32_t* a, const uint32_t* b) {
    asm volatile(
        "mma.sync.aligned.m16n8k16.row.col.f32.f16.f16.f32 "
        "{%0,%1,%2,%3}, {%4,%5,%6,%7}, {%8,%9}, {%0,%1,%2,%3};"
        : "+f"(c[0]), "+f"(c[1]), "+f"(c[2]), "+f"(c[3])
        : "r"(a[0]), "r"(a[1]), "r"(a[2]), "r"(a[3]), "r"(b[0]), "r"(b[1]));
}
// dot of 8 fp16 pairs (as uint4) accumulated in fp32
__device__ __forceinline__ float dot8(uint4 a, uint4 c) {
    const __half2* pa = (const __half2*)&a;
    const __half2* pc = (const __half2*)&c;
    float s = 0.f;
#pragma unroll
    for (int i = 0; i < 4; i++) {
        float2 fa = __half22float2(pa[i]);
        float2 fc = __half22float2(pc[i]);
        s += fa.x * fc.x + fa.y * fc.y;
    }
    return s;
}

// ---------------------------------------------------------------------------
// fp16 GEMM: C[M,N] = A[M,K] @ B[N,K]^T  (fp32 accumulate)
// flags: bit0 relu, bit1 write fp16 (Ch), bit2 write fp32 (Cf).
// 256 threads, 128x256 CTA tile, 64x64 warp tile, BK=32, 4-stage pipeline.
// ---------------------------------------------------------------------------
__global__ __launch_bounds__(256, 1)
void mm_fp16_kernel(const __half* __restrict__ A, const __half* __restrict__ B,
                    float* __restrict__ Cf, __half* __restrict__ Ch,
                    const float* __restrict__ bias, int N, int K, int flags)
{
    extern __shared__ char smem[];
    const uint32_t sb = smem_u32(smem);
    const int tid  = threadIdx.x;
    const int wid  = tid >> 5;
    const int lane = tid & 31;
    const int bm   = blockIdx.y * BM;
    const int bn   = blockIdx.x * BN;
    const int wm   = (wid >> 2) * 64;   // 2 warps in M
    const int wn   = (wid & 3) * 64;    // 4 warps in N
    const int ntiles = K / BK;

    // -------- producer addressing --------
    const int rowA = tid & 127;
    const int sgA  = tid >> 7;          // 0/1; covers segs sgA, sgA+2
    const __half* gA = A + (size_t)(bm + rowA) * K;
    const __half* gB = B + (size_t)(bn + tid) * K;   // 256 B-rows, 1 per thread
    const uint32_t doffA = (uint32_t)rowA * ROWB;
    const uint32_t doffB = (uint32_t)tid * ROWB;

    auto issue = [&](int kt, int s) {
        const uint32_t st = sb + (uint32_t)s * STG_BYTES;
        const size_t kof = (size_t)kt * BK;
#pragma unroll
        for (int qq = 0; qq < 2; qq++) {
            const int seg = sgA + qq * 2;
            cp16(st + STG_A + doffA + seg * 16, gA + kof + seg * 8);
        }
#pragma unroll
        for (int seg = 0; seg < 4; seg++)
            cp16(st + STG_B + doffB + seg * 16, gB + kof + seg * 8);
        asm volatile("cp.async.commit_group;" ::: "memory");
    };

    float acc[4][8][4];
#pragma unroll
    for (int i = 0; i < 4; i++)
#pragma unroll
        for (int j = 0; j < 8; j++)
#pragma unroll
            for (int l = 0; l < 4; l++) acc[i][j][l] = 0.f;

    issue(0, 0);
    issue(1, 1);
    issue(2, 2);

    // ldmatrix lane addressing
    const int arow  = lane & 15;
    const int acol8 = (lane >> 4) * 8;
    const int brow  = (lane & 7) + ((lane >> 4) << 3);
    const int bcol8 = ((lane >> 3) & 1) * 8;

    for (int kt = 0; kt < ntiles; kt++) {
        if (kt < ntiles - 2)
            asm volatile("cp.async.wait_group 2;" ::: "memory");
        else if (kt == ntiles - 2)
            asm volatile("cp.async.wait_group 1;" ::: "memory");
        else
            asm volatile("cp.async.wait_group 0;" ::: "memory");
        __syncthreads();

        const uint32_t stg = sb + (uint32_t)(kt % NSTG) * STG_BYTES;
#pragma unroll
        for (int ks = 0; ks < 2; ks++) {
            const int kb = ks * 16;
            uint32_t af[4][4], bf[4][4];
#pragma unroll
            for (int mt = 0; mt < 4; mt++) {
                const uint32_t off =
                    (uint32_t)((wm + mt * 16 + arow) * KSTRIDE + kb + acol8) * 2;
                ldsm4(af[mt], stg + STG_A + off);
            }
#pragma unroll
            for (int nt2 = 0; nt2 < 4; nt2++) {
                const uint32_t off =
                    (uint32_t)((wn + nt2 * 16 + brow) * KSTRIDE + kb + bcol8) * 2;
                ldsm4(bf[nt2], stg + STG_B + off);
            }
#pragma unroll
            for (int mt = 0; mt < 4; mt++)
#pragma unroll
                for (int nt = 0; nt < 8; nt++)
                    mma16816(acc[mt][nt], af[mt], &bf[nt >> 1][(nt & 1) * 2]);
        }
        if (kt + 3 < ntiles) issue(kt + 3, (kt + 3) % NSTG);
    }

    // -------- epilogue --------
    const int g = lane >> 2;
    const int t = lane & 3;
#pragma unroll
    for (int mt = 0; mt < 4; mt++)
#pragma unroll
        for (int nt = 0; nt < 8; nt++) {
            const int gcol = bn + wn + nt * 8 + t * 2;
            float b0 = 0.f, b1 = 0.f;
            if (bias) { b0 = __ldg(&bias[gcol]); b1 = __ldg(&bias[gcol + 1]); }
#pragma unroll
            for (int half_ = 0; half_ < 2; half_++) {
                const int grow = bm + wm + mt * 16 + g + half_ * 8;
                float v0 = acc[mt][nt][half_ * 2 + 0] + b0;
                float v1 = acc[mt][nt][half_ * 2 + 1] + b1;
                if (flags & 1) { v0 = fmaxf(v0, 0.f); v1 = fmaxf(v1, 0.f); }
                const size_t o = (size_t)grow * N + gcol;
                if (flags & 4)
                    *(float2*)(Cf + o) = make_float2(v0, v1);
                if (flags & 2)
                    *(__half2*)(Ch + o) =
                        __halves2half2(__float2half_rn(v0), __float2half_rn(v1));
            }
        }
}

// ---------------------------------------------------------------------------
// ALL weight transposes in ONE launch.  blockIdx.z selects the matrix.
// ---------------------------------------------------------------------------
__global__ void thalf_all_kernel(const float* __restrict__ Wq, const float* __restrict__ Wk,
                                 const float* __restrict__ Wv, const float* __restrict__ Wo,
                                 const float* __restrict__ W1, const float* __restrict__ W2,
                                 __half* __restrict__ wqkv, __half* __restrict__ wo,
                                 __half* __restrict__ w1, __half* __restrict__ w2)
{
    const float* W;
    __half* T;
    int Kd, Nd;
    switch (blockIdx.z) {
        case 0: W = Wq; T = wqkv;                           Kd = CDIM; Nd = CDIM; break;
        case 1: W = Wk; T = wqkv + (size_t)CDIM * CDIM;     Kd = CDIM; Nd = CDIM; break;
        case 2: W = Wv; T = wqkv + (size_t)2 * CDIM * CDIM; Kd = CDIM; Nd = CDIM; break;
        case 3: W = Wo; T = wo;                             Kd = CDIM; Nd = CDIM; break;
        case 4: W = W1; T = w1;                             Kd = CDIM; Nd = HDIM; break;
        default: W = W2; T = w2;                            Kd = HDIM; Nd = CDIM; break;
    }
    const int bx = blockIdx.x * 32;
    const int by = blockIdx.y * 32;
    if (bx >= Nd || by >= Kd) return;

    __shared__ float t[32][33];
    const int x = threadIdx.x, y0 = threadIdx.y;
#pragma unroll
    for (int dy = 0; dy < 32; dy += 8)
        t[y0 + dy][x] = W[(size_t)(by + y0 + dy) * Nd + bx + x];
    __syncthreads();
#pragma unroll
    for (int dy = 0; dy < 32; dy += 8)
        T[(size_t)(bx + y0 + dy) * Kd + by + x] = __float2half_rn(t[x][y0 + dy]);
}

// Elementwise fp32 -> fp16 (for x).
__global__ void tohalf_kernel(const float* __restrict__ in, __half* __restrict__ o,
                              int n4)
{
    int i = blockIdx.x * blockDim.x + threadIdx.x;
    if (i >= n4) return;
    float4 a = ((const float4*)in)[i];
    ((__half2*)o)[i * 2]     = __halves2half2(__float2half_rn(a.x), __float2half_rn(a.y));
    ((__half2*)o)[i * 2 + 1] = __halves2half2(__float2half_rn(a.z), __float2half_rn(a.w));
}

// ---------------------------------------------------------------------------
// Neighbor attention (K=8); fp16 qkv[M][3072] = q|k|v, fp32 math, fp16 ctx out.
// ---------------------------------------------------------------------------
__global__ __launch_bounds__(256)
void attn_kernel(const __half* __restrict__ qkv, const float* __restrict__ radj,
                 const int* __restrict__ inxs, __half* __restrict__ ctx)
{
    const int bt = blockIdx.x;
    const int b = bt >> 10;
    const int tid = threadIdx.x;
    const int wid = tid >> 5, lid = tid & 31;

    __shared__ float s_scores[KNEI];
    __shared__ int s_rows[KNEI];
    if (tid < KNEI) s_rows[tid] = b * TSEQ + inxs[(size_t)bt * KNEI + tid];
    __syncthreads();

    const uint4* qv = (const uint4*)(qkv + (size_t)bt * QKVLD);
    const uint4* kv = (const uint4*)(qkv + (size_t)s_rows[wid] * QKVLD + CDIM);
    float sum = 0.f;
#pragma unroll
    for (int e = lid; e < CDIM / 8; e += 32)
        sum += dot8(qv[e], kv[e]);
#pragma unroll
    for (int o = 16; o > 0; o >>= 1) sum += __shfl_xor_sync(0xffffffffu, sum, o);
    if (lid == 0)
        s_scores[wid] = sum * 0.03125f + radj[(size_t)bt * KNEI + wid];
    __syncthreads();

    float w[KNEI];
    float mx = s_scores[0];
#pragma unroll
    for (int j = 1; j < KNEI; j++) mx = fmaxf(mx, s_scores[j]);
    float den = 0.f;
#pragma unroll
    for (int j = 0; j < KNEI; j++) { w[j] = expf(s_scores[j] - mx); den += w[j]; }
    const float inv = 1.f / den;

    float a0 = 0.f, a1 = 0.f, a2 = 0.f, a3 = 0.f;
#pragma unroll
    for (int j = 0; j < KNEI; j++) {
        const uint2 vv =
            ((const uint2*)(qkv + (size_t)s_rows[j] * QKVLD + 2 * CDIM))[tid];
        const __half2* pv = (const __half2*)&vv;
        const float2 f0 = __half22float2(pv[0]);
        const float2 f1 = __half22float2(pv[1]);
        const float wj = w[j] * inv;
        a0 = fmaf(wj, f0.x, a0); a1 = fmaf(wj, f0.y, a1);
        a2 = fmaf(wj, f1.x, a2); a3 = fmaf(wj, f1.y, a3);
    }
    uint2 ov;
    ((__half2*)&ov)[0] = __halves2half2(__float2half_rn(a0), __float2half_rn(a1));
    ((__half2*)&ov)[1] = __halves2half2(__float2half_rn(a2), __float2half_rn(a3));
    ((uint2*)(ctx + (size_t)bt * CDIM))[tid] = ov;
}

// ---------------------------------------------------------------------------
// Fused residual (+optional relu) LayerNorm.  Residual branch hb is fp16.
// ---------------------------------------------------------------------------
__global__ __launch_bounds__(256)
void ln_kernel(const float* __restrict__ a, const __half* __restrict__ hb,
               const float* __restrict__ g, const float* __restrict__ beta,
               float* __restrict__ out, __half* __restrict__ oh, int relu_h)
{
    __shared__ float sh1[8], sh2[8];
    const int bt = blockIdx.x;
    const int tid = threadIdx.x;
    const int wid = tid >> 5, lid = tid & 31;
    const size_t base = (size_t)bt * CDIM;

    float4 z = ((const float4*)(a + base))[tid];
    const uint2 hv = ((const uint2*)(hb + base))[tid];
    const __half2* ph = (const __half2*)&hv;
    const float2 h01 = __half22float2(ph[0]);
    const float2 h23 = __half22float2(ph[1]);
    float hx = h01.x, hy = h01.y, hz = h23.x, hw = h23.y;
    if (relu_h) {
        hx = fmaxf(hx, 0.f); hy = fmaxf(hy, 0.f);
        hz = fmaxf(hz, 0.f); hw = fmaxf(hw, 0.f);
    }
    z.x += hx; z.y += hy; z.z += hz; z.w += hw;

    float s = z.x + z.y + z.z + z.w;
    float ss = z.x * z.x + z.y * z.y + z.z * z.z + z.w * z.w;
#pragma unroll
    for (int o = 16; o > 0; o >>= 1) {
        s += __shfl_xor_sync(0xffffffffu, s, o);
        ss += __shfl_xor_sync(0xffffffffu, ss, o);
    }
    if (lid == 0) { sh1[wid] = s; sh2[wid] = ss; }
    __syncthreads();
    float ts = 0.f, tss = 0.f;
#pragma unroll
    for (int j = 0; j < 8; j++) { ts += sh1[j]; tss += sh2[j]; }

    const float mean = ts * (1.f / CDIM);
    const float var = tss * (1.f / CDIM) - mean * mean;
    const float rstd = rsqrtf(var + 1e-5f);

    const float4 gg = ((const float4*)g)[tid];
    const float4 bb = ((const float4*)beta)[tid];
    float4 o4;
    o4.x = (z.x - mean) * rstd * gg.x + bb.x;
    o4.y = (z.y - mean) * rstd * gg.y + bb.y;
    o4.z = (z.z - mean) * rstd * gg.z + bb.z;
    o4.w = (z.w - mean) * rstd * gg.w + bb.w;
    ((float4*)(out + base))[tid] = o4;
    if (oh) {
        const size_t b2 = (size_t)bt * (CDIM / 2) + tid * 2;
        ((__half2*)oh)[b2] =
            __halves2half2(__float2half_rn(o4.x), __float2half_rn(o4.y));
        ((__half2*)oh)[b2 + 1] =
            __halves2half2(__float2half_rn(o4.z), __float2half_rn(o4.w));
    }
}

// ---------------------------------------------------------------------------
// Launch
// ---------------------------------------------------------------------------
extern "C" void kernel_launch(void* const* d_in, const int* in_sizes, int n_in,
                              void* d_out, int out_size)
{
    const float* x    = (const float*)d_in[0];
    const float* radj = (const float*)d_in[1];
    const int*   inxs = (const int*)  d_in[2];
    const float* Wq   = (const float*)d_in[3];
    const float* Wk   = (const float*)d_in[4];
    const float* Wv   = (const float*)d_in[5];
    const float* Wo   = (const float*)d_in[6];
    const float* ln1g = (const float*)d_in[7];
    const float* ln1b = (const float*)d_in[8];
    const float* W1   = (const float*)d_in[9];
    const float* b1   = (const float*)d_in[10];
    const float* W2   = (const float*)d_in[11];
    const float* b2   = (const float*)d_in[12];
    const float* ln2g = (const float*)d_in[13];
    const float* ln2b = (const float*)d_in[14];
    float* out = (float*)d_out;

    float *y;
    __half *qkv, *ctx, *h1, *yh, *f16, *xh, *hid, *wqkvh, *woh, *w1h, *w2h;
    cudaGetSymbolAddress((void**)&qkv, g_qkv);
    cudaGetSymbolAddress((void**)&ctx, g_ctx);
    cudaGetSymbolAddress((void**)&h1, g_h1);
    cudaGetSymbolAddress((void**)&y, g_y);
    cudaGetSymbolAddress((void**)&yh, g_yh);
    cudaGetSymbolAddress((void**)&f16, g_f16);
    cudaGetSymbolAddress((void**)&xh, g_xh);
    cudaGetSymbolAddress((void**)&hid, g_hid);
    cudaGetSymbolAddress((void**)&wqkvh, g_wqkvh);
    cudaGetSymbolAddress((void**)&woh, g_woh);
    cudaGetSymbolAddress((void**)&w1h, g_w1h);
    cudaGetSymbolAddress((void**)&w2h, g_w2h);

    cudaFuncSetAttribute(mm_fp16_kernel,
                         cudaFuncAttributeMaxDynamicSharedMemorySize, MM_SMEM);

    const dim3 b256(256);

    thalf_all_kernel<<<dim3(HDIM / 32, HDIM / 32, 6), dim3(32, 8)>>>(
        Wq, Wk, Wv, Wo, W1, W2, wqkvh, woh, w1h, w2h);
    tohalf_kernel<<<(MDIM * CDIM / 4 + 255) / 256, b256>>>(x, xh, MDIM * CDIM / 4);

    const dim3 gQKV(QKVLD / BN, MDIM / BM);  // (12, 128)
    const dim3 gCC(CDIM / BN, MDIM / BM);    // (4, 128)
    const dim3 gCH(HDIM / BN, MDIM / BM);    // (6, 128)

    const __half* a16 = xh;
    for (int hop = 0; hop < 2; hop++) {
        mm_fp16_kernel<<<gQKV, 256, MM_SMEM>>>(a16, wqkvh, nullptr, qkv,
                                               nullptr, QKVLD, CDIM, 2);
        attn_kernel<<<MDIM, b256>>>(qkv, radj, inxs, ctx);
        mm_fp16_kernel<<<gCC, 256, MM_SMEM>>>(ctx, woh, nullptr, h1,
                                              nullptr, CDIM, CDIM, 2);
        a16 = h1;
    }

    // y = LN(x + relu(h));  + fp16 copy for FFN input
    ln_kernel<<<MDIM, b256>>>(x, h1, ln1g, ln1b, y, yh, 1);
    // hid = relu(y @ W1 + b1)  -> fp16
    mm_fp16_kernel<<<gCH, 256, MM_SMEM>>>(yh, w1h, nullptr, hid, b1, HDIM, CDIM, 1 | 2);
    // f = hid @ W2 + b2  -> fp16
    mm_fp16_kernel<<<gCC, 256, MM_SMEM>>>(hid, w2h, nullptr, f16, b2, CDIM, HDIM, 2);
    // out = LN(y + f)
    ln_kernel<<<MDIM, b256>>>(y, f16, ln2g, ln2b, out, nullptr, 0);
}